// round 9
// baseline (speedup 1.0000x reference)
#include <cuda_runtime.h>
#include <cuda_fp16.h>
#include <math.h>
#include <stdint.h>

// ---------------- problem constants ----------------
#define BB   16
#define HH   56
#define WW   56
#define CC   384
#define C2   192
#define NHD  8
#define HD2  24
#define MM   (BB*HH*WW)        // 50176 tokens
#define HW   (HH*WW)           // 3136
#define KT   112               // attn key tile: 3136 = 28*112
#define NSPLIT 4               // attention kv splits (7 tiles each)
#define SCALE_F 0.20412414523193154f

// ---------------- scratch (device globals; no allocation allowed) ----------------
__device__ __align__(16) __half g_xn  [(size_t)MM*CC];
__device__ __align__(16) __half g_xen [(size_t)MM*C2];
__device__ __align__(16) __half g_q   [(size_t)MM*CC];
__device__ __align__(16) __half g_cut [(size_t)MM*C2];
__device__ __align__(16) __half g_lx  [(size_t)MM*CC];
__device__ __align__(16) __half g_clx [(size_t)MM*CC];
__device__ __align__(16) __half g_a   [(size_t)MM*CC];
__device__ __align__(16) float  g_kv  [(size_t)MM*CC];    // attn input stays fp32
__device__ __align__(16) __half g_ef  [(size_t)MM*C2];
__device__ __align__(16) __half g_efc [(size_t)MM*C2];
__device__ __align__(16) __half g_xe2 [(size_t)MM*C2];
__device__ __align__(16) float  g_m   [(size_t)BB*NHD*49*HD2];
__device__ __align__(16) float  g_o   [(size_t)BB*NHD*49*HD2];
__device__ __align__(16) float  g_op  [(size_t)BB*NHD*NSPLIT*49*HD2];  // split partials
__device__ __align__(16) float  g_mx  [(size_t)BB*NHD*NSPLIT*49];
__device__ __align__(16) float  g_sm2 [(size_t)BB*NHD*NSPLIT*49];
__device__ __align__(16) __half g_cat [(size_t)MM*768];

// transposed (+zero-padded) weights, fp16: Bt[n*K + k] = h(W[k*N + n])
__device__ __align__(16) __half g_tq    [384*384];
__device__ __align__(16) __half g_tl    [384*384];
__device__ __align__(16) __half g_ta    [384*384];
__device__ __align__(16) __half g_tkv   [384*384];
__device__ __align__(16) __half g_tqcut [256*384];
__device__ __align__(16) __half g_tefore[256*192];
__device__ __align__(16) __half g_teback[256*192];
__device__ __align__(16) __half g_tproj [384*768];
__device__ __align__(16) __half g_tproje[256*768];

// ---------------- PTX helpers (sm_80+ features only; no 'a'-gated instrs) ----------------
__device__ __forceinline__ uint32_t smem_u32(const void* p) {
    uint32_t r;
    asm("{ .reg .u64 t; cvta.to.shared.u64 t, %1; cvt.u32.u64 %0, t; }" : "=r"(r) : "l"(p));
    return r;
}
__device__ __forceinline__ void cp_async16(uint32_t dst, const void* src) {
    asm volatile("cp.async.ca.shared.global [%0], [%1], 16;" :: "r"(dst), "l"(src) : "memory");
}
__device__ __forceinline__ void cp_commit() {
    asm volatile("cp.async.commit_group;" ::: "memory");
}
template<int N>
__device__ __forceinline__ void cp_wait() {
    asm volatile("cp.async.wait_group %0;" :: "n"(N) : "memory");
}
__device__ __forceinline__ void ldsm_x4(uint32_t& r0, uint32_t& r1, uint32_t& r2, uint32_t& r3,
                                        uint32_t addr) {
    asm volatile("ldmatrix.sync.aligned.m8n8.x4.shared.b16 {%0,%1,%2,%3}, [%4];"
                 : "=r"(r0), "=r"(r1), "=r"(r2), "=r"(r3) : "r"(addr));
}
__device__ __forceinline__ void mma_f16(float* c, const uint32_t* a, uint32_t b0, uint32_t b1) {
    asm volatile(
        "mma.sync.aligned.m16n8k16.row.col.f32.f16.f16.f32 "
        "{%0,%1,%2,%3}, {%4,%5,%6,%7}, {%8,%9}, {%0,%1,%2,%3};"
        : "+f"(c[0]), "+f"(c[1]), "+f"(c[2]), "+f"(c[3])
        : "r"(a[0]), "r"(a[1]), "r"(a[2]), "r"(a[3]), "r"(b0), "r"(b1));
}

// ---------------- batched weight transpose + pad + fp16 (one launch) ----------------
__global__ void transpose_all_kernel(
    const float* __restrict__ q_w,     const float* __restrict__ l_w,
    const float* __restrict__ a_w,     const float* __restrict__ kv_w,
    const float* __restrict__ qcut_w,  const float* __restrict__ efore_w,
    const float* __restrict__ eback_w, const float* __restrict__ proj_w,
    const float* __restrict__ proje_w,
    __half* __restrict__ tq,     __half* __restrict__ tl,
    __half* __restrict__ ta,     __half* __restrict__ tkv,
    __half* __restrict__ tqcut,  __half* __restrict__ tefore,
    __half* __restrict__ teback, __half* __restrict__ tproj,
    __half* __restrict__ tproje)
{
    int idx = blockIdx.x * 256 + threadIdx.x;   // grid exactly 1277952/256 = 4992
    const float* src; __half* dst; int K, N, off;
    if      (idx <  147456) { src=q_w;     dst=tq;     K=384; N=384; off=idx; }
    else if (idx <  294912) { src=l_w;     dst=tl;     K=384; N=384; off=idx- 147456; }
    else if (idx <  442368) { src=a_w;     dst=ta;     K=384; N=384; off=idx- 294912; }
    else if (idx <  589824) { src=kv_w;    dst=tkv;    K=384; N=384; off=idx- 442368; }
    else if (idx <  688128) { src=qcut_w;  dst=tqcut;  K=384; N=192; off=idx- 589824; }
    else if (idx <  737280) { src=efore_w; dst=tefore; K=192; N=192; off=idx- 688128; }
    else if (idx <  786432) { src=eback_w; dst=teback; K=192; N=192; off=idx- 737280; }
    else if (idx < 1081344) { src=proj_w;  dst=tproj;  K=768; N=384; off=idx- 786432; }
    else                    { src=proje_w; dst=tproje; K=768; N=192; off=idx-1081344; }
    int n = off / K, k = off % K;
    float v = (n < N) ? src[(size_t)k * N + n] : 0.f;
    dst[off] = __float2half(v);
}

// ---------------- fp16 tensor-core GEMM: 3-stage cp.async pipeline, 1 sync/chunk ----------------
#define SSH 72
#define STAGE_BYTES (128 * SSH * 2 * 2)     // A+B per stage = 36864 B
#define GEMM_SMEM (3 * STAGE_BYTES)         // 110592 B (3 stages, 2 CTAs/SM)
__global__ __launch_bounds__(256, 2)
void h16_gemm_kernel(const __half* __restrict__ A, const __half* __restrict__ Bt,
                     const float* __restrict__ bias, float* __restrict__ Cf,
                     __half* __restrict__ Ch, int N, int K, int act)
{
    extern __shared__ __half smh[];
    const int tid = threadIdx.x, lane = tid & 31, wid = tid >> 5;
    const int bn = blockIdx.x, bm = blockIdx.y;
    const int warpM = (wid & 3) * 32, warpN = (wid >> 2) * 64;

    const __half* Ab = A  + (size_t)bm * 128 * K;
    const __half* Bb = Bt + (size_t)bn * 128 * K;
    uint32_t sb = smem_u32(smh);
    const int ldrow = tid >> 3;
    const int ldch  = tid & 7;

    float acc[2][8][4];
    #pragma unroll
    for (int i = 0; i < 2; i++)
        #pragma unroll
        for (int j = 0; j < 8; j++)
            #pragma unroll
            for (int t = 0; t < 4; t++) acc[i][j][t] = 0.f;

    const int NC = K >> 6;
    const uint32_t aoff = (uint32_t)((lane & 7) + ((lane >> 3) & 1) * 8) * 144 + (lane >> 4) * 16;
    const uint32_t boff = (uint32_t)((lane & 7) + (lane >> 4) * 8) * 144 + ((lane >> 3) & 1) * 16;

    // prefetch chunks 0 and 1 into stages 0, 1 (separate commit groups)
    #pragma unroll
    for (int it = 0; it < 4; it++) {
        int row = ldrow + it * 32;
        uint32_t o = (uint32_t)row * 144 + ldch * 16;
        cp_async16(sb + o, Ab + (size_t)row * K + ldch * 8);
        cp_async16(sb + 128 * SSH * 2 + o, Bb + (size_t)row * K + ldch * 8);
    }
    cp_commit();
    if (NC > 1) {
        uint32_t stage = sb + STAGE_BYTES;
        const __half* ga = Ab + 64;
        const __half* gb = Bb + 64;
        #pragma unroll
        for (int it = 0; it < 4; it++) {
            int row = ldrow + it * 32;
            uint32_t o = (uint32_t)row * 144 + ldch * 16;
            cp_async16(stage + o, ga + (size_t)row * K + ldch * 8);
            cp_async16(stage + 128 * SSH * 2 + o, gb + (size_t)row * K + ldch * 8);
        }
        cp_commit();
    }

    int scur = 0;                       // stage of chunk c
    for (int c = 0; c < NC; c++) {
        if (c + 1 < NC) cp_wait<1>(); else cp_wait<0>();
        __syncthreads();                // single barrier per chunk

        // issue loads for chunk c+2 AFTER the barrier (safe: stage (c+2)%3 ==
        // (c-1)%3, whose readers all finished MMA(c-1) before this barrier)
        if (c + 2 < NC) {
            int snxt = scur + 2; if (snxt >= 3) snxt -= 3;
            uint32_t stage = sb + (uint32_t)snxt * STAGE_BYTES;
            const __half* ga = Ab + (c + 2) * 64;
            const __half* gb = Bb + (c + 2) * 64;
            #pragma unroll
            for (int it = 0; it < 4; it++) {
                int row = ldrow + it * 32;
                uint32_t o = (uint32_t)row * 144 + ldch * 16;
                cp_async16(stage + o, ga + (size_t)row * K + ldch * 8);
                cp_async16(stage + 128 * SSH * 2 + o, gb + (size_t)row * K + ldch * 8);
            }
            cp_commit();
        }

        uint32_t sA  = sb + (uint32_t)scur * STAGE_BYTES + (uint32_t)warpM * 144 + aoff;
        uint32_t sBv = sb + (uint32_t)scur * STAGE_BYTES + 128 * SSH * 2 + (uint32_t)warpN * 144 + boff;

        #pragma unroll
        for (int ks = 0; ks < 4; ks++) {
            uint32_t afr[2][4];
            ldsm_x4(afr[0][0], afr[0][1], afr[0][2], afr[0][3], sA + ks * 32);
            ldsm_x4(afr[1][0], afr[1][1], afr[1][2], afr[1][3], sA + 16 * 144 + ks * 32);
            #pragma unroll
            for (int ntp = 0; ntp < 4; ntp++) {
                uint32_t b0, b1, b2, b3;
                ldsm_x4(b0, b1, b2, b3, sBv + (uint32_t)ntp * 16 * 144 + ks * 32);
                mma_f16(acc[0][ntp * 2],     afr[0], b0, b1);
                mma_f16(acc[1][ntp * 2],     afr[1], b0, b1);
                mma_f16(acc[0][ntp * 2 + 1], afr[0], b2, b3);
                mma_f16(acc[1][ntp * 2 + 1], afr[1], b2, b3);
            }
        }
        scur++; if (scur >= 3) scur -= 3;
    }

    #pragma unroll
    for (int mt = 0; mt < 2; mt++) {
        size_t row0 = (size_t)bm * 128 + warpM + mt * 16 + (lane >> 2);
        #pragma unroll
        for (int nt = 0; nt < 8; nt++) {
            int gcol = bn * 128 + warpN + nt * 8 + (lane & 3) * 2;
            if (gcol < N) {
                float bs0 = bias[gcol], bs1 = bias[gcol + 1];
                float v0 = acc[mt][nt][0] + bs0;
                float v1 = acc[mt][nt][1] + bs1;
                float v2 = acc[mt][nt][2] + bs0;
                float v3 = acc[mt][nt][3] + bs1;
                if (act == 1) {
                    v0 = 0.5f*v0*(1.f+erff(v0*0.70710678118654752f));
                    v1 = 0.5f*v1*(1.f+erff(v1*0.70710678118654752f));
                    v2 = 0.5f*v2*(1.f+erff(v2*0.70710678118654752f));
                    v3 = 0.5f*v3*(1.f+erff(v3*0.70710678118654752f));
                }
                if (Ch) {
                    __half2 h0; h0.x = __float2half(v0); h0.y = __float2half(v1);
                    __half2 h1; h1.x = __float2half(v2); h1.y = __float2half(v3);
                    *(__half2*)(Ch + row0 * (size_t)N + gcol) = h0;
                    *(__half2*)(Ch + (row0 + 8) * (size_t)N + gcol) = h1;
                } else {
                    float2 p0; p0.x = v0; p0.y = v1;
                    float2 p1; p1.x = v2; p1.y = v3;
                    *(float2*)(Cf + row0 * (size_t)N + gcol) = p0;
                    *(float2*)(Cf + (row0 + 8) * (size_t)N + gcol) = p1;
                }
            }
        }
    }
}

// ---------------- LayerNorm: one warp per row, both tensors in one launch ----------------
#define LN_BLOCKS_X (MM / 8)     // 6272 blocks for xn
__global__ void ln_kernel(const float* __restrict__ x, const float* __restrict__ w,
                          const float* __restrict__ b, __half* __restrict__ out,
                          const float* __restrict__ xe, const float* __restrict__ we,
                          const float* __restrict__ be, __half* __restrict__ oute)
{
    int blk = blockIdx.x;
    const float* xx; const float* ww; const float* bb; __half* oo; int C;
    if (blk < LN_BLOCKS_X) { xx = x;  ww = w;  bb = b;  oo = out;  C = CC; }
    else                   { xx = xe; ww = we; bb = be; oo = oute; C = C2; blk -= LN_BLOCKS_X; }
    int row = blk * 8 + (threadIdx.x >> 5);
    int lane = threadIdx.x & 31;
    const float* xr = xx + (size_t)row * C;
    __half* orow = oo + (size_t)row * C;

    int n = C >> 5;
    float local[12];
    float s = 0.f;
    for (int i = 0; i < n; i++) { float v = xr[lane + 32 * i]; local[i] = v; s += v; }
    #pragma unroll
    for (int o = 16; o; o >>= 1) s += __shfl_xor_sync(0xffffffffu, s, o);
    float mean = s / (float)C;

    float ss = 0.f;
    for (int i = 0; i < n; i++) { float d = local[i] - mean; ss += d * d; }
    #pragma unroll
    for (int o = 16; o; o >>= 1) ss += __shfl_xor_sync(0xffffffffu, ss, o);
    float rstd = rsqrtf(ss / (float)C + 1e-6f);

    for (int i = 0; i < n; i++) {
        int cidx = lane + 32 * i;
        orow[cidx] = __float2half((local[i] - mean) * rstd * ww[cidx] + bb[cidx]);
    }
}

// ---------------- pooled shortcut queries + scl GEMM + SCALE fold (half2 loads) ----------------
__global__ void pool_scl_kernel(const __half* __restrict__ xn, const __half* __restrict__ xen,
                                const float* __restrict__ sw, const float* __restrict__ sb,
                                float* __restrict__ mout)
{
    __shared__ float pooled[576];
    int blk = blockIdx.x; int b = blk / 49, qi = blk % 49;
    int py = qi / 7, px = qi % 7;
    int tid = threadIdx.x;    // 192 threads

    for (int ch2 = tid; ch2 < 288; ch2 += 192) {
        float sx = 0.f, sy = 0.f;
        if (ch2 < 192) {
            const __half2* base = (const __half2*)(xn + ((size_t)(b * HH + py * 8) * WW + px * 8) * CC) + ch2;
            #pragma unroll
            for (int hy = 0; hy < 8; hy++)
                #pragma unroll
                for (int wx = 0; wx < 8; wx++) {
                    float2 v = __half22float2(base[(size_t)(hy * WW + wx) * 192]);
                    sx += v.x; sy += v.y;
                }
        } else {
            const __half2* base = (const __half2*)(xen + ((size_t)(b * HH + py * 8) * WW + px * 8) * C2) + (ch2 - 192);
            #pragma unroll
            for (int hy = 0; hy < 8; hy++)
                #pragma unroll
                for (int wx = 0; wx < 8; wx++) {
                    float2 v = __half22float2(base[(size_t)(hy * WW + wx) * 96]);
                    sx += v.x; sy += v.y;
                }
        }
        pooled[ch2 * 2]     = sx * (1.0f / 64.0f);
        pooled[ch2 * 2 + 1] = sy * (1.0f / 64.0f);
    }
    __syncthreads();

    int j = tid;
    float a = sb[j];
    for (int kk = 0; kk < 576; kk++) a += pooled[kk] * sw[(size_t)kk * C2 + j];
    a *= SCALE_F;
    mout[((size_t)(b * NHD + j / HD2) * 49 + qi) * HD2 + (j % HD2)] = a;
}

// ---------------- depthwise 7x7 conv: register sliding window, FMA-bound ----------------
__global__ __launch_bounds__(224)
void dwconv7_kernel(const __half* __restrict__ in, const float* __restrict__ w,
                    const float* __restrict__ bias, __half* __restrict__ out, int C)
{
    __shared__ float s_in[20][336];
    __shared__ float s_w[16][49];
    __shared__ float s_b[16];
    __shared__ __align__(16) __half s_out[196][16];

    int nchunk = C >> 4;
    int b  = blockIdx.z / nchunk;
    int c0 = (blockIdx.z % nchunk) << 4;
    int ty0 = blockIdx.y * 14, tx0 = blockIdx.x * 14;
    int tid = threadIdx.x;   // 224

    for (int idx = tid; idx < 800; idx += 224) {
        int p = idx >> 1, h8 = idx & 1;
        int iy = p / 20, ix = p % 20;
        int gy = ty0 + iy - 3, gx = tx0 + ix - 3;
        __half hb[8];
        uint4 z; z.x = z.y = z.z = z.w = 0u;
        *(uint4*)hb = z;
        if (gy >= 0 && gy < HH && gx >= 0 && gx < WW)
            *(uint4*)hb = *(const uint4*)(in + (((size_t)b * HH + gy) * WW + gx) * C + c0 + h8 * 8);
        #pragma unroll
        for (int j = 0; j < 8; j++)
            s_in[iy][ix * 16 + h8 * 8 + j] = __half2float(hb[j]);
    }
    for (int idx = tid; idx < 784; idx += 224)
        s_w[idx / 49][idx % 49] = w[(size_t)(c0 + idx / 49) * 49 + idx % 49];
    if (tid < 16) s_b[tid] = bias[c0 + tid];
    __syncthreads();

    int r = tid >> 4, cc = tid & 15;
    float acc[14];
    #pragma unroll
    for (int x = 0; x < 14; x++) acc[x] = s_b[cc];
    #pragma unroll
    for (int ky = 0; ky < 7; ky++) {
        float wk[7];
        #pragma unroll
        for (int kx = 0; kx < 7; kx++) wk[kx] = s_w[cc][ky * 7 + kx];
        float v[20];
        #pragma unroll
        for (int ix = 0; ix < 20; ix++) v[ix] = s_in[r + ky][ix * 16 + cc];
        #pragma unroll
        for (int kx = 0; kx < 7; kx++)
            #pragma unroll
            for (int x = 0; x < 14; x++) acc[x] += wk[kx] * v[x + kx];
    }
    #pragma unroll
    for (int x = 0; x < 14; x++) s_out[r * 14 + x][cc] = __float2half(acc[x]);
    __syncthreads();

    for (int idx = tid; idx < 392; idx += 224) {
        int p = idx >> 1, h8 = idx & 1;
        int oy = ty0 + p / 14, ox = tx0 + p % 14;
        *(uint4*)(out + (((size_t)b * HH + oy) * WW + ox) * C + c0 + h8 * 8) =
            *(uint4*)&s_out[p][h8 * 8];
    }
}

// ---------------- flash attention, split-K x4 (7 key tiles per CTA) ----------------
#define OM   0
#define OK0  1372
#define OK1  4508
#define OV0  7644
#define OV1  10780
#define OS   13916
#define OMX  19404
#define OSM  19453
#define OSC  19502
#define ATTN_SMEM (19551 * 4)

__global__ __launch_bounds__(256)
void attn_kernel(const float* __restrict__ kvb, const float* __restrict__ m,
                 float* __restrict__ op, float* __restrict__ mxg, float* __restrict__ smg)
{
    extern __shared__ float sm[];
    const int split = blockIdx.x & (NSPLIT - 1);
    const int bh = blockIdx.x >> 2, b = bh >> 3, h = bh & 7;
    const int tid = threadIdx.x, lane = tid & 31, wid = tid >> 5;
    uint32_t sb = smem_u32(sm);

    const float* kbase = kvb + (size_t)b * HW * CC + h * HD2;
    const float* vbase = kbase + C2;
    const int T0 = split * 7;

    for (int idx = tid; idx < 1176; idx += 256) {
        int q = idx / 24, d = idx % 24;
        sm[OM + q * 28 + d] = m[(size_t)bh * 1176 + idx];
    }
    if (tid < 49) { sm[OMX + tid] = -1e30f; sm[OSM + tid] = 0.f; }

    const int pvc = tid & 3, pvg = tid >> 2;
    const int pq0 = (pvg / 8) * 7, pd0 = (pvg % 8) * 3;
    const bool pv_act = (tid < 224);
    float acc[7][3];
    #pragma unroll
    for (int i = 0; i < 7; i++)
        #pragma unroll
        for (int j = 0; j < 3; j++) acc[i][j] = 0.f;

    const int sqb = tid / 28, skb = tid % 28;
    const int sq0 = sqb * 7;
    const bool sc_act = (tid < 196);

    {
        int kt0 = T0 * KT;
        for (int idx = tid; idx < 1344; idx += 256) {
            int mat = idx / 672, r = (idx % 672) / 6, p = idx % 6;
            const float* src = (mat ? vbase : kbase) + (size_t)(kt0 + r) * CC + p * 4;
            uint32_t dst = sb + ((mat ? OV0 : OK0) + r * 28 + p * 4) * 4;
            cp_async16(dst, src);
        }
        cp_commit();
    }

    for (int t = 0; t < 7; t++) {
        int buf = t & 1;
        if (t + 1 < 7) {
            int kt1 = (T0 + t + 1) * KT;
            int nb = buf ^ 1;
            for (int idx = tid; idx < 1344; idx += 256) {
                int mat = idx / 672, r = (idx % 672) / 6, p = idx % 6;
                const float* src = (mat ? vbase : kbase) + (size_t)(kt1 + r) * CC + p * 4;
                uint32_t dst = sb + ((mat ? (nb ? OV1 : OV0) : (nb ? OK1 : OK0)) + r * 28 + p * 4) * 4;
                cp_async16(dst, src);
            }
            cp_commit();
            cp_wait<1>();
        } else {
            cp_wait<0>();
        }
        __syncthreads();

        if (sc_act) {
            const float4* k4 = (const float4*)(sm + (buf ? OK1 : OK0));
            const float4* m4 = (const float4*)(sm + OM);
            float sc[7][4];
            #pragma unroll
            for (int i = 0; i < 7; i++)
                #pragma unroll
                for (int j = 0; j < 4; j++) sc[i][j] = 0.f;
            #pragma unroll
            for (int d4 = 0; d4 < 6; d4++) {
                float4 kv4[4], mm4[7];
                #pragma unroll
                for (int j = 0; j < 4; j++) kv4[j] = k4[(skb + 28 * j) * 7 + d4];
                #pragma unroll
                for (int i = 0; i < 7; i++) mm4[i] = m4[(sq0 + i) * 7 + d4];
                #pragma unroll
                for (int i = 0; i < 7; i++)
                    #pragma unroll
                    for (int j = 0; j < 4; j++)
                        sc[i][j] += mm4[i].x * kv4[j].x + mm4[i].y * kv4[j].y
                                  + mm4[i].z * kv4[j].z + mm4[i].w * kv4[j].w;
            }
            #pragma unroll
            for (int i = 0; i < 7; i++)
                #pragma unroll
                for (int j = 0; j < 4; j++)
                    sm[OS + (sq0 + i) * 112 + skb + 28 * j] = sc[i][j];
        }
        __syncthreads();

        for (int q = wid; q < 49; q += 8) {
            float* row = sm + OS + q * 112;
            float v0 = row[lane], v1 = row[lane + 32], v2 = row[lane + 64];
            float v3 = (lane < 16) ? row[lane + 96] : -1e30f;
            float tmax = fmaxf(fmaxf(v0, v1), fmaxf(v2, v3));
            #pragma unroll
            for (int off = 16; off; off >>= 1)
                tmax = fmaxf(tmax, __shfl_xor_sync(0xffffffffu, tmax, off));
            float mold = sm[OMX + q];
            float mnew = fmaxf(mold, tmax);
            float e0 = expf(v0 - mnew), e1 = expf(v1 - mnew), e2 = expf(v2 - mnew);
            float e3 = (lane < 16) ? expf(v3 - mnew) : 0.f;
            row[lane] = e0; row[lane + 32] = e1; row[lane + 64] = e2;
            if (lane < 16) row[lane + 96] = e3;
            float tsum = e0 + e1 + e2 + e3;
            #pragma unroll
            for (int off = 16; off; off >>= 1)
                tsum += __shfl_xor_sync(0xffffffffu, tsum, off);
            if (lane == 0) {
                float scale = expf(mold - mnew);
                sm[OSC + q] = scale;
                sm[OSM + q] = sm[OSM + q] * scale + tsum;
                sm[OMX + q] = mnew;
            }
        }
        __syncthreads();

        if (pv_act) {
            #pragma unroll
            for (int i = 0; i < 7; i++) {
                float scl = sm[OSC + pq0 + i];
                #pragma unroll
                for (int j = 0; j < 3; j++) acc[i][j] *= scl;
            }
            const float* vb = sm + (buf ? OV1 : OV0);
            for (int lk = 0; lk < 28; lk++) {
                int kk = pvc * 28 + lk;
                float vv0 = vb[kk * 28 + pd0];
                float vv1 = vb[kk * 28 + pd0 + 1];
                float vv2 = vb[kk * 28 + pd0 + 2];
                #pragma unroll
                for (int i = 0; i < 7; i++) {
                    float pp = sm[OS + (pq0 + i) * 112 + kk];
                    acc[i][0] += pp * vv0;
                    acc[i][1] += pp * vv1;
                    acc[i][2] += pp * vv2;
                }
            }
        }
        __syncthreads();
    }

    if (pv_act) {
        #pragma unroll
        for (int i = 0; i < 7; i++)
            #pragma unroll
            for (int j = 0; j < 3; j++)
                sm[OS + ((pq0 + i) * 24 + pd0 + j) * 4 + pvc] = acc[i][j];
    }
    __syncthreads();
    size_t base = (size_t)(bh * NSPLIT + split);
    for (int idx = tid; idx < 1176; idx += 256) {
        float r = sm[OS + idx * 4] + sm[OS + idx * 4 + 1]
                + sm[OS + idx * 4 + 2] + sm[OS + idx * 4 + 3];
        op[base * 1176 + idx] = r;
    }
    if (tid < 49) {
        mxg[base * 49 + tid] = sm[OMX + tid];
        smg[base * 49 + tid] = sm[OSM + tid];
    }
}

// ---------------- attention split merge (log-sum-exp combine) ----------------
__global__ void attn_merge_kernel(const float* __restrict__ op, const float* __restrict__ mxg,
                                  const float* __restrict__ smg, float* __restrict__ o)
{
    __shared__ float wgt[NSPLIT][49];
    __shared__ float den[49];
    int bh = blockIdx.x, tid = threadIdx.x;   // 256 threads
    if (tid < 49) {
        float mx[NSPLIT];
        #pragma unroll
        for (int s = 0; s < NSPLIT; s++) mx[s] = mxg[(size_t)(bh * NSPLIT + s) * 49 + tid];
        float ms = fmaxf(fmaxf(mx[0], mx[1]), fmaxf(mx[2], mx[3]));
        float d = 0.f;
        #pragma unroll
        for (int s = 0; s < NSPLIT; s++) {
            float ww = expf(mx[s] - ms);
            wgt[s][tid] = ww;
            d += smg[(size_t)(bh * NSPLIT + s) * 49 + tid] * ww;
        }
        den[tid] = d;
    }
    __syncthreads();
    for (int idx = tid; idx < 1176; idx += 256) {
        int q = idx / 24;
        float r = 0.f;
        #pragma unroll
        for (int s = 0; s < NSPLIT; s++)
            r += op[(size_t)(bh * NSPLIT + s) * 1176 + idx] * wgt[s][q];
        o[(size_t)bh * 1176 + idx] = r / den[q];
    }
}

// ---------------- concat [q*a | bilinear(o) | cut*xe2], fused upsample ----------------
__global__ void cat_kernel(const __half* __restrict__ q, const __half* __restrict__ a,
                           const float* __restrict__ o, const __half* __restrict__ cut,
                           const __half* __restrict__ xe2, __half* __restrict__ cat)
{
    size_t row = blockIdx.x;
    int t = threadIdx.x;                 // 192 threads, 4 halves each
    __half v[4];
    if (t < 96) {
        int c = t * 4;
        #pragma unroll
        for (int j = 0; j < 4; j++)
            v[j] = __float2half(__half2float(q[row * 384 + c + j]) *
                                __half2float(a[row * 384 + c + j]));
    } else if (t < 144) {
        int c = (t - 96) * 4;
        int b = (int)(row / HW); int rem = (int)(row % HW);
        int y = rem / WW, x = rem % WW;
        int h = c / HD2, d = c % HD2;
        float fy = (y + 0.5f) * 0.125f - 0.5f;
        float fx = (x + 0.5f) * 0.125f - 0.5f;
        int y0 = (int)floorf(fy); float ty = fy - (float)y0;
        int x0 = (int)floorf(fx); float tx = fx - (float)x0;
        int y0c = max(y0, 0), y1c = min(y0 + 1, 6);
        int x0c = max(x0, 0), x1c = min(x0 + 1, 6);
        const float* ob = o + ((size_t)(b * NHD + h) * 49) * HD2 + d;
        float4 v00 = *(const float4*)(ob + (y0c * 7 + x0c) * HD2);
        float4 v01 = *(const float4*)(ob + (y0c * 7 + x1c) * HD2);
        float4 v10 = *(const float4*)(ob + (y1c * 7 + x0c) * HD2);
        float4 v11 = *(const float4*)(ob + (y1c * 7 + x1c) * HD2);
        float w00 = (1.f - ty) * (1.f - tx), w01 = (1.f - ty) * tx;
        float w10 = ty * (1.f - tx), w11 = ty * tx;
        v[0] = __float2half(w00 * v00.x + w01 * v01.x + w10 * v10.x + w11 * v11.x);
        v[1] = __float2half(w00 * v00.y + w01 * v01.y + w10 * v10.y + w11 * v11.y);
        v[2] = __float2half(w00 * v00.z + w01 * v01.z + w10 * v10.z + w11 * v11.z);
        v[3] = __float2half(w00 * v00.w + w01 * v01.w + w10 * v10.w + w11 * v11.w);
    } else {
        int c = (t - 144) * 4;
        #pragma unroll
        for (int j = 0; j < 4; j++)
            v[j] = __float2half(__half2float(cut[row * 192 + c + j]) *
                                __half2float(xe2[row * 192 + c + j]));
    }
    *(uint2*)(cat + row * 768 + t * 4) = *(uint2*)v;
}

// ---------------- launch ----------------
extern "C" void kernel_launch(void* const* d_in, const int* in_sizes, int n_in,
                              void* d_out, int out_size)
{
    const float* x       = (const float*)d_in[0];
    const float* x_e     = (const float*)d_in[1];
    const float* norm_w  = (const float*)d_in[2];
    const float* norm_b  = (const float*)d_in[3];
    const float* norme_w = (const float*)d_in[4];
    const float* norme_b = (const float*)d_in[5];
    const float* q_w     = (const float*)d_in[6];
    const float* q_b     = (const float*)d_in[7];
    const float* qcut_w  = (const float*)d_in[8];
    const float* qcut_b  = (const float*)d_in[9];
    const float* a_w     = (const float*)d_in[10];
    const float* a_b     = (const float*)d_in[11];
    const float* l_w     = (const float*)d_in[12];
    const float* l_b     = (const float*)d_in[13];
    const float* conv_w  = (const float*)d_in[14];
    const float* conv_b  = (const float*)d_in[15];
    const float* econv_w = (const float*)d_in[16];
    const float* econv_b = (const float*)d_in[17];
    const float* efore_w = (const float*)d_in[18];
    const float* efore_b = (const float*)d_in[19];
    const float* eback_w = (const float*)d_in[20];
    const float* eback_b = (const float*)d_in[21];
    const float* kv_w    = (const float*)d_in[22];
    const float* kv_b    = (const float*)d_in[23];
    const float* scl_w   = (const float*)d_in[24];
    const float* scl_b   = (const float*)d_in[25];
    const float* proj_w  = (const float*)d_in[26];
    const float* proj_b  = (const float*)d_in[27];
    const float* proje_w = (const float*)d_in[28];
    const float* proje_b = (const float*)d_in[29];
    float* out = (float*)d_out;
    float* out_x  = out;
    float* out_xe = out + (size_t)MM * CC;

    __half *xn,*xen,*qb,*cutb,*lx,*clx,*ab,*ef,*efc,*xe2,*catb;
    __half *tq,*tl,*ta,*tkv,*tqcut,*tefore,*teback,*tproj,*tproje;
    float *kvb,*mb,*ob,*opb,*mxb,*smb;
    cudaGetSymbolAddress((void**)&xn,   g_xn);
    cudaGetSymbolAddress((void**)&xen,  g_xen);
    cudaGetSymbolAddress((void**)&qb,   g_q);
    cudaGetSymbolAddress((void**)&cutb, g_cut);
    cudaGetSymbolAddress((void**)&lx,   g_lx);
    cudaGetSymbolAddress((void**)&clx,  g_clx);
    cudaGetSymbolAddress((void**)&ab,   g_a);
    cudaGetSymbolAddress((void**)&kvb,  g_kv);
    cudaGetSymbolAddress((void**)&ef,   g_ef);
    cudaGetSymbolAddress((void**)&efc,  g_efc);
    cudaGetSymbolAddress((void**)&xe2,  g_xe2);
    cudaGetSymbolAddress((void**)&mb,   g_m);
    cudaGetSymbolAddress((void**)&ob,   g_o);
    cudaGetSymbolAddress((void**)&opb,  g_op);
    cudaGetSymbolAddress((void**)&mxb,  g_mx);
    cudaGetSymbolAddress((void**)&smb,  g_sm2);
    cudaGetSymbolAddress((void**)&catb, g_cat);
    cudaGetSymbolAddress((void**)&tq,     g_tq);
    cudaGetSymbolAddress((void**)&tl,     g_tl);
    cudaGetSymbolAddress((void**)&ta,     g_ta);
    cudaGetSymbolAddress((void**)&tkv,    g_tkv);
    cudaGetSymbolAddress((void**)&tqcut,  g_tqcut);
    cudaGetSymbolAddress((void**)&tefore, g_tefore);
    cudaGetSymbolAddress((void**)&teback, g_teback);
    cudaGetSymbolAddress((void**)&tproj,  g_tproj);
    cudaGetSymbolAddress((void**)&tproje, g_tproje);

    cudaFuncSetAttribute(h16_gemm_kernel, cudaFuncAttributeMaxDynamicSharedMemorySize, GEMM_SMEM);
    cudaFuncSetAttribute(attn_kernel, cudaFuncAttributeMaxDynamicSharedMemorySize, ATTN_SMEM);

    // 0) all weight transposes in one launch
    transpose_all_kernel<<<4992, 256>>>(q_w, l_w, a_w, kv_w, qcut_w, efore_w, eback_w,
                                        proj_w, proje_w,
                                        tq, tl, ta, tkv, tqcut, tefore, teback, tproj, tproje);

    // 1) both LayerNorms in one launch
    ln_kernel<<<LN_BLOCKS_X + MM / 8, 256>>>(x, norm_w, norm_b, xn,
                                             x_e, norme_w, norme_b, xen);

    // 2) pooled shortcut queries -> m (scaled, fp32)
    pool_scl_kernel<<<BB * 49, 192>>>(xn, xen, scl_w, scl_b, mb);

    // 3) q / cut / lx(gelu) GEMMs (fp16 tensor cores)
    dim3 gN384(3, MM / 128), gN192(2, MM / 128);
    h16_gemm_kernel<<<gN384, 256, GEMM_SMEM>>>(xn, tq,    q_b,    nullptr, qb,   384, 384, 0);
    h16_gemm_kernel<<<gN192, 256, GEMM_SMEM>>>(xn, tqcut, qcut_b, nullptr, cutb, 192, 384, 0);
    h16_gemm_kernel<<<gN384, 256, GEMM_SMEM>>>(xn, tl,    l_b,    nullptr, lx,   384, 384, 1);

    // 4) depthwise conv on lx, then a / kv GEMMs (kv -> fp32 for attention)
    dwconv7_kernel<<<dim3(4, 4, BB * (CC / 16)), 224>>>(lx, conv_w, conv_b, clx, CC);
    h16_gemm_kernel<<<gN384, 256, GEMM_SMEM>>>(clx, ta,  a_b,  nullptr, ab, 384, 384, 0);
    h16_gemm_kernel<<<gN384, 256, GEMM_SMEM>>>(lx,  tkv, kv_b, kvb, nullptr, 384, 384, 0);

    // 5) flash attention (split-K x4) + merge
    attn_kernel<<<BB * NHD * NSPLIT, 256, ATTN_SMEM>>>(kvb, mb, opb, mxb, smb);
    attn_merge_kernel<<<BB * NHD, 256>>>(opb, mxb, smb, ob);

    // 6) x_e depthwise branch
    h16_gemm_kernel<<<gN192, 256, GEMM_SMEM>>>(xen, tefore, efore_b, nullptr, ef, 192, 192, 0);
    dwconv7_kernel<<<dim3(4, 4, BB * (C2 / 16)), 224>>>(ef, econv_w, econv_b, efc, C2);
    h16_gemm_kernel<<<gN192, 256, GEMM_SMEM>>>(efc, teback, eback_b, nullptr, xe2, 192, 192, 0);

    // 7) concat (fused bilinear upsample) + final projections (fp32 out)
    cat_kernel<<<MM, 192>>>(qb, ab, ob, cutb, xe2, catb);
    h16_gemm_kernel<<<gN384, 256, GEMM_SMEM>>>(catb, tproj,  proj_b,  out_x,  nullptr, 384, 768, 0);
    h16_gemm_kernel<<<gN192, 256, GEMM_SMEM>>>(catb, tproje, proje_b, out_xe, nullptr, 192, 768, 0);
}

// round 10
// speedup vs baseline: 1.1428x; 1.1428x over previous
#include <cuda_runtime.h>
#include <cuda_fp16.h>
#include <math.h>
#include <stdint.h>

// ---------------- problem constants ----------------
#define BB   16
#define HH   56
#define WW   56
#define CC   384
#define C2   192
#define NHD  8
#define HD2  24
#define MM   (BB*HH*WW)        // 50176 tokens
#define HW   (HH*WW)           // 3136
#define KT   112               // attn key tile: 3136 = 28*112
#define NSPLIT 4               // attention kv splits (7 tiles each)
#define SCALE_F 0.20412414523193154f

// ---------------- scratch (device globals; no allocation allowed) ----------------
__device__ __align__(16) __half g_xn  [(size_t)MM*CC];
__device__ __align__(16) __half g_xen [(size_t)MM*C2];
__device__ __align__(16) __half g_q   [(size_t)MM*CC];
__device__ __align__(16) __half g_cut [(size_t)MM*C2];
__device__ __align__(16) __half g_lx  [(size_t)MM*CC];
__device__ __align__(16) __half g_clx [(size_t)MM*CC];
__device__ __align__(16) __half g_a   [(size_t)MM*CC];
__device__ __align__(16) float  g_kv  [(size_t)MM*CC];    // attn input stays fp32
__device__ __align__(16) __half g_ef  [(size_t)MM*C2];
__device__ __align__(16) __half g_efc [(size_t)MM*C2];
__device__ __align__(16) __half g_xe2 [(size_t)MM*C2];
__device__ __align__(16) float  g_m   [(size_t)BB*NHD*49*HD2];
__device__ __align__(16) float  g_o   [(size_t)BB*NHD*49*HD2];
__device__ __align__(16) float  g_op  [(size_t)BB*NHD*NSPLIT*49*HD2];
__device__ __align__(16) float  g_mx  [(size_t)BB*NHD*NSPLIT*49];
__device__ __align__(16) float  g_sm2 [(size_t)BB*NHD*NSPLIT*49];
__device__ __align__(16) __half g_cat [(size_t)MM*768];

// fused transposed weights (fp16) + biases (fp32)
__device__ __align__(16) __half g_w3 [1024*384];   // [q | l | qcut(pad 256)] rows, K=384
__device__ __align__(16) float  g_b3 [1024];
__device__ __align__(16) __half g_w2 [640*768];    // [proj | proje(pad)] rows, K=768
__device__ __align__(16) float  g_b2 [640];
__device__ __align__(16) __half g_tkv   [384*384];
__device__ __align__(16) __half g_ta    [384*384];
__device__ __align__(16) __half g_tefore[256*192];
__device__ __align__(16) __half g_teback[256*192];

// ---------------- PTX helpers (sm_80+ features only; no 'a'-gated instrs) ----------------
__device__ __forceinline__ uint32_t smem_u32(const void* p) {
    uint32_t r;
    asm("{ .reg .u64 t; cvta.to.shared.u64 t, %1; cvt.u32.u64 %0, t; }" : "=r"(r) : "l"(p));
    return r;
}
__device__ __forceinline__ void cp_async16(uint32_t dst, const void* src) {
    asm volatile("cp.async.ca.shared.global [%0], [%1], 16;" :: "r"(dst), "l"(src) : "memory");
}
__device__ __forceinline__ void cp_commit() {
    asm volatile("cp.async.commit_group;" ::: "memory");
}
template<int N>
__device__ __forceinline__ void cp_wait() {
    asm volatile("cp.async.wait_group %0;" :: "n"(N) : "memory");
}
__device__ __forceinline__ void ldsm_x4(uint32_t& r0, uint32_t& r1, uint32_t& r2, uint32_t& r3,
                                        uint32_t addr) {
    asm volatile("ldmatrix.sync.aligned.m8n8.x4.shared.b16 {%0,%1,%2,%3}, [%4];"
                 : "=r"(r0), "=r"(r1), "=r"(r2), "=r"(r3) : "r"(addr));
}
__device__ __forceinline__ void mma_f16(float* c, const uint32_t* a, uint32_t b0, uint32_t b1) {
    asm volatile(
        "mma.sync.aligned.m16n8k16.row.col.f32.f16.f16.f32 "
        "{%0,%1,%2,%3}, {%4,%5,%6,%7}, {%8,%9}, {%0,%1,%2,%3};"
        : "+f"(c[0]), "+f"(c[1]), "+f"(c[2]), "+f"(c[3])
        : "r"(a[0]), "r"(a[1]), "r"(a[2]), "r"(a[3]), "r"(b0), "r"(b1));
}
__device__ __forceinline__ float gelu_f(float v) {
    return 0.5f * v * (1.f + erff(v * 0.70710678118654752f));
}

// ---------------- batched weight transpose + pad + fp16 + bias concat (one launch) ----------------
__global__ void transpose_all_kernel(
    const float* __restrict__ q_w,     const float* __restrict__ l_w,
    const float* __restrict__ a_w,     const float* __restrict__ kv_w,
    const float* __restrict__ qcut_w,  const float* __restrict__ efore_w,
    const float* __restrict__ eback_w, const float* __restrict__ proj_w,
    const float* __restrict__ proje_w,
    const float* __restrict__ q_b,     const float* __restrict__ l_b,
    const float* __restrict__ qcut_b,  const float* __restrict__ proj_b,
    const float* __restrict__ proje_b,
    __half* __restrict__ w3, float* __restrict__ b3,
    __half* __restrict__ w2, float* __restrict__ b2,
    __half* __restrict__ tkv, __half* __restrict__ ta,
    __half* __restrict__ tefore, __half* __restrict__ teback)
{
    int idx = blockIdx.x * 256 + threadIdx.x;   // grid 4999 covers 1279616
    if (idx < 393216) {                         // w3 [1024 x 384]
        int n = idx / 384, k = idx % 384;
        float v;
        if      (n <  384) v = q_w[(size_t)k * 384 + n];
        else if (n <  768) v = l_w[(size_t)k * 384 + (n - 384)];
        else if (n <  960) v = qcut_w[(size_t)k * 192 + (n - 768)];
        else               v = 0.f;
        w3[idx] = __float2half(v);
    } else if (idx < 884736) {                  // w2 [640 x 768]
        int off = idx - 393216;
        int n = off / 768, k = off % 768;
        float v;
        if      (n < 384) v = proj_w[(size_t)k * 384 + n];
        else if (n < 576) v = proje_w[(size_t)k * 192 + (n - 384)];
        else              v = 0.f;
        w2[off] = __float2half(v);
    } else if (idx < 1032192) {                 // tkv
        int off = idx - 884736;
        int n = off / 384, k = off % 384;
        tkv[off] = __float2half(kv_w[(size_t)k * 384 + n]);
    } else if (idx < 1179648) {                 // ta
        int off = idx - 1032192;
        int n = off / 384, k = off % 384;
        ta[off] = __float2half(a_w[(size_t)k * 384 + n]);
    } else if (idx < 1228800) {                 // tefore [256 x 192]
        int off = idx - 1179648;
        int n = off / 192, k = off % 192;
        tefore[off] = __float2half((n < 192) ? efore_w[(size_t)k * 192 + n] : 0.f);
    } else if (idx < 1277952) {                 // teback [256 x 192]
        int off = idx - 1228800;
        int n = off / 192, k = off % 192;
        teback[off] = __float2half((n < 192) ? eback_w[(size_t)k * 192 + n] : 0.f);
    } else if (idx < 1278976) {                 // b3 [1024]
        int j = idx - 1277952;
        float v;
        if      (j <  384) v = q_b[j];
        else if (j <  768) v = l_b[j - 384];
        else if (j <  960) v = qcut_b[j - 768];
        else               v = 0.f;
        b3[j] = v;
    } else if (idx < 1279616) {                 // b2 [640]
        int j = idx - 1278976;
        float v;
        if      (j < 384) v = proj_b[j];
        else if (j < 576) v = proje_b[j - 384];
        else              v = 0.f;
        b2[j] = v;
    }
}

// ================= GEMM pipeline core (round-8 proven: 2-stage, 2 syncs/chunk) =================
#define SSH 72
#define STAGE_BYTES (128 * SSH * 2 * 2)     // A+B per stage = 36864 B
#define GEMM_SMEM (2 * STAGE_BYTES)         // 73728 B
#define GEMM_PIPE_BODY                                                                   \
    float acc[2][8][4];                                                                  \
    _Pragma("unroll")                                                                    \
    for (int i = 0; i < 2; i++)                                                          \
        _Pragma("unroll")                                                                \
        for (int j = 0; j < 8; j++)                                                      \
            _Pragma("unroll")                                                            \
            for (int t = 0; t < 4; t++) acc[i][j][t] = 0.f;                              \
    const int NC = K >> 6;                                                               \
    const uint32_t aoff = (uint32_t)((lane & 7) + ((lane >> 3) & 1) * 8) * 144 + (lane >> 4) * 16; \
    const uint32_t boff = (uint32_t)((lane & 7) + (lane >> 4) * 8) * 144 + ((lane >> 3) & 1) * 16; \
    _Pragma("unroll")                                                                    \
    for (int it = 0; it < 4; it++) {                                                     \
        int row = ldrow + it * 32;                                                       \
        uint32_t o = (uint32_t)row * 144 + ldch * 16;                                    \
        cp_async16(sb + o, Ab + (size_t)row * K + ldch * 8);                             \
        cp_async16(sb + 128 * SSH * 2 + o, Bb + (size_t)row * K + ldch * 8);             \
    }                                                                                    \
    cp_commit();                                                                         \
    for (int c = 0; c < NC; c++) {                                                       \
        int buf = c & 1;                                                                 \
        if (c + 1 < NC) {                                                                \
            uint32_t stage = sb + (uint32_t)((c + 1) & 1) * STAGE_BYTES;                 \
            const __half* ga = Ab + (c + 1) * 64;                                        \
            const __half* gb = Bb + (c + 1) * 64;                                        \
            _Pragma("unroll")                                                            \
            for (int it = 0; it < 4; it++) {                                             \
                int row = ldrow + it * 32;                                               \
                uint32_t o = (uint32_t)row * 144 + ldch * 16;                            \
                cp_async16(stage + o, ga + (size_t)row * K + ldch * 8);                  \
                cp_async16(stage + 128 * SSH * 2 + o, gb + (size_t)row * K + ldch * 8);  \
            }                                                                            \
            cp_commit();                                                                 \
            cp_wait<1>();                                                                \
        } else {                                                                         \
            cp_wait<0>();                                                                \
        }                                                                                \
        __syncthreads();                                                                 \
        uint32_t sA  = sb + (uint32_t)buf * STAGE_BYTES + (uint32_t)warpM * 144 + aoff;  \
        uint32_t sBv = sb + (uint32_t)buf * STAGE_BYTES + 128 * SSH * 2 + (uint32_t)warpN * 144 + boff; \
        _Pragma("unroll")                                                                \
        for (int ks = 0; ks < 4; ks++) {                                                 \
            uint32_t afr[2][4];                                                          \
            ldsm_x4(afr[0][0], afr[0][1], afr[0][2], afr[0][3], sA + ks * 32);           \
            ldsm_x4(afr[1][0], afr[1][1], afr[1][2], afr[1][3], sA + 16 * 144 + ks * 32);\
            _Pragma("unroll")                                                            \
            for (int ntp = 0; ntp < 4; ntp++) {                                          \
                uint32_t b0, b1, b2, b3;                                                 \
                ldsm_x4(b0, b1, b2, b3, sBv + (uint32_t)ntp * 16 * 144 + ks * 32);       \
                mma_f16(acc[0][ntp * 2],     afr[0], b0, b1);                            \
                mma_f16(acc[1][ntp * 2],     afr[1], b0, b1);                            \
                mma_f16(acc[0][ntp * 2 + 1], afr[0], b2, b3);                            \
                mma_f16(acc[1][ntp * 2 + 1], afr[1], b2, b3);                            \
            }                                                                            \
        }                                                                                \
        __syncthreads();                                                                 \
    }

// ---------------- generic fp16 GEMM: C = A @ Bt^T + bias (half or float out) ----------------
__global__ __launch_bounds__(256, 2)
void h16_gemm_kernel(const __half* __restrict__ A, const __half* __restrict__ Bt,
                     const float* __restrict__ bias, float* __restrict__ Cf,
                     __half* __restrict__ Ch, int N, int K)
{
    extern __shared__ __half smh[];
    const int tid = threadIdx.x, lane = tid & 31, wid = tid >> 5;
    const int bn = blockIdx.x, bm = blockIdx.y;
    const int warpM = (wid & 3) * 32, warpN = (wid >> 2) * 64;
    const __half* Ab = A  + (size_t)bm * 128 * K;
    const __half* Bb = Bt + (size_t)bn * 128 * K;
    uint32_t sb = smem_u32(smh);
    const int ldrow = tid >> 3;
    const int ldch  = tid & 7;

    GEMM_PIPE_BODY

    #pragma unroll
    for (int mt = 0; mt < 2; mt++) {
        size_t row0 = (size_t)bm * 128 + warpM + mt * 16 + (lane >> 2);
        #pragma unroll
        for (int nt = 0; nt < 8; nt++) {
            int gcol = bn * 128 + warpN + nt * 8 + (lane & 3) * 2;
            if (gcol < N) {
                float bs0 = bias[gcol], bs1 = bias[gcol + 1];
                float v0 = acc[mt][nt][0] + bs0;
                float v1 = acc[mt][nt][1] + bs1;
                float v2 = acc[mt][nt][2] + bs0;
                float v3 = acc[mt][nt][3] + bs1;
                if (Ch) {
                    __half2 h0; h0.x = __float2half(v0); h0.y = __float2half(v1);
                    __half2 h1; h1.x = __float2half(v2); h1.y = __float2half(v3);
                    *(__half2*)(Ch + row0 * (size_t)N + gcol) = h0;
                    *(__half2*)(Ch + (row0 + 8) * (size_t)N + gcol) = h1;
                } else {
                    float2 p0; p0.x = v0; p0.y = v1;
                    float2 p1; p1.x = v2; p1.y = v3;
                    *(float2*)(Cf + row0 * (size_t)N + gcol) = p0;
                    *(float2*)(Cf + (row0 + 8) * (size_t)N + gcol) = p1;
                }
            }
        }
    }
}

// ---------------- routed fp16 GEMM: fused multi-output epilogue ----------------
// mode 0 (N=1024, A=xn):  col<384 -> o0 (q, half, ld 384)
//                         col<768 -> o1 (lx, half, ld 384, gelu)
//                         col<960 -> o2 (cut, half, ld 192); else pad skip
// mode 1 (N=640, A=cat):  col<384 -> f0 (out_x, float, ld 384)
//                         col<576 -> f1 (out_xe, float, ld 192); else pad skip
__global__ __launch_bounds__(256, 2)
void h16_gemm_routed(const __half* __restrict__ A, const __half* __restrict__ Bt,
                     const float* __restrict__ bias,
                     __half* __restrict__ o0, __half* __restrict__ o1, __half* __restrict__ o2,
                     float* __restrict__ f0, float* __restrict__ f1,
                     int N, int K, int mode)
{
    extern __shared__ __half smh[];
    const int tid = threadIdx.x, lane = tid & 31, wid = tid >> 5;
    const int bn = blockIdx.x, bm = blockIdx.y;
    const int warpM = (wid & 3) * 32, warpN = (wid >> 2) * 64;
    const __half* Ab = A  + (size_t)bm * 128 * K;
    const __half* Bb = Bt + (size_t)bn * 128 * K;
    uint32_t sb = smem_u32(smh);
    const int ldrow = tid >> 3;
    const int ldch  = tid & 7;

    GEMM_PIPE_BODY

    #pragma unroll
    for (int mt = 0; mt < 2; mt++) {
        size_t row0 = (size_t)bm * 128 + warpM + mt * 16 + (lane >> 2);
        #pragma unroll
        for (int nt = 0; nt < 8; nt++) {
            int gcol = bn * 128 + warpN + nt * 8 + (lane & 3) * 2;
            float bs0 = bias[gcol], bs1 = bias[gcol + 1];
            float v0 = acc[mt][nt][0] + bs0;
            float v1 = acc[mt][nt][1] + bs1;
            float v2 = acc[mt][nt][2] + bs0;
            float v3 = acc[mt][nt][3] + bs1;
            if (mode == 0) {
                __half* dst; int col, ldc;
                if (gcol < 384)      { dst = o0; col = gcol;       ldc = 384; }
                else if (gcol < 768) { dst = o1; col = gcol - 384; ldc = 384;
                                       v0 = gelu_f(v0); v1 = gelu_f(v1);
                                       v2 = gelu_f(v2); v3 = gelu_f(v3); }
                else if (gcol < 960) { dst = o2; col = gcol - 768; ldc = 192; }
                else continue;
                __half2 h0; h0.x = __float2half(v0); h0.y = __float2half(v1);
                __half2 h1; h1.x = __float2half(v2); h1.y = __float2half(v3);
                *(__half2*)(dst + row0 * (size_t)ldc + col) = h0;
                *(__half2*)(dst + (row0 + 8) * (size_t)ldc + col) = h1;
            } else {
                float* dst; int col, ldc;
                if (gcol < 384)      { dst = f0; col = gcol;       ldc = 384; }
                else if (gcol < 576) { dst = f1; col = gcol - 384; ldc = 192; }
                else continue;
                float2 p0; p0.x = v0; p0.y = v1;
                float2 p1; p1.x = v2; p1.y = v3;
                *(float2*)(dst + row0 * (size_t)ldc + col) = p0;
                *(float2*)(dst + (row0 + 8) * (size_t)ldc + col) = p1;
            }
        }
    }
}

// ---------------- LayerNorm: one warp per row, both tensors in one launch ----------------
#define LN_BLOCKS_X (MM / 8)
__global__ void ln_kernel(const float* __restrict__ x, const float* __restrict__ w,
                          const float* __restrict__ b, __half* __restrict__ out,
                          const float* __restrict__ xe, const float* __restrict__ we,
                          const float* __restrict__ be, __half* __restrict__ oute)
{
    int blk = blockIdx.x;
    const float* xx; const float* ww; const float* bb; __half* oo; int C;
    if (blk < LN_BLOCKS_X) { xx = x;  ww = w;  bb = b;  oo = out;  C = CC; }
    else                   { xx = xe; ww = we; bb = be; oo = oute; C = C2; blk -= LN_BLOCKS_X; }
    int row = blk * 8 + (threadIdx.x >> 5);
    int lane = threadIdx.x & 31;
    const float* xr = xx + (size_t)row * C;
    __half* orow = oo + (size_t)row * C;

    int n = C >> 5;
    float local[12];
    float s = 0.f;
    for (int i = 0; i < n; i++) { float v = xr[lane + 32 * i]; local[i] = v; s += v; }
    #pragma unroll
    for (int o = 16; o; o >>= 1) s += __shfl_xor_sync(0xffffffffu, s, o);
    float mean = s / (float)C;

    float ss = 0.f;
    for (int i = 0; i < n; i++) { float d = local[i] - mean; ss += d * d; }
    #pragma unroll
    for (int o = 16; o; o >>= 1) ss += __shfl_xor_sync(0xffffffffu, ss, o);
    float rstd = rsqrtf(ss / (float)C + 1e-6f);

    for (int i = 0; i < n; i++) {
        int cidx = lane + 32 * i;
        orow[cidx] = __float2half((local[i] - mean) * rstd * ww[cidx] + bb[cidx]);
    }
}

// ---------------- pooled shortcut queries + scl GEMM + SCALE fold (half2 loads) ----------------
__global__ void pool_scl_kernel(const __half* __restrict__ xn, const __half* __restrict__ xen,
                                const float* __restrict__ sw, const float* __restrict__ sb,
                                float* __restrict__ mout)
{
    __shared__ float pooled[576];
    int blk = blockIdx.x; int b = blk / 49, qi = blk % 49;
    int py = qi / 7, px = qi % 7;
    int tid = threadIdx.x;    // 192 threads

    for (int ch2 = tid; ch2 < 288; ch2 += 192) {
        float sx = 0.f, sy = 0.f;
        if (ch2 < 192) {
            const __half2* base = (const __half2*)(xn + ((size_t)(b * HH + py * 8) * WW + px * 8) * CC) + ch2;
            #pragma unroll
            for (int hy = 0; hy < 8; hy++)
                #pragma unroll
                for (int wx = 0; wx < 8; wx++) {
                    float2 v = __half22float2(base[(size_t)(hy * WW + wx) * 192]);
                    sx += v.x; sy += v.y;
                }
        } else {
            const __half2* base = (const __half2*)(xen + ((size_t)(b * HH + py * 8) * WW + px * 8) * C2) + (ch2 - 192);
            #pragma unroll
            for (int hy = 0; hy < 8; hy++)
                #pragma unroll
                for (int wx = 0; wx < 8; wx++) {
                    float2 v = __half22float2(base[(size_t)(hy * WW + wx) * 96]);
                    sx += v.x; sy += v.y;
                }
        }
        pooled[ch2 * 2]     = sx * (1.0f / 64.0f);
        pooled[ch2 * 2 + 1] = sy * (1.0f / 64.0f);
    }
    __syncthreads();

    int j = tid;
    float a = sb[j];
    for (int kk = 0; kk < 576; kk++) a += pooled[kk] * sw[(size_t)kk * C2 + j];
    a *= SCALE_F;
    mout[((size_t)(b * NHD + j / HD2) * 49 + qi) * HD2 + (j % HD2)] = a;
}

// ---------------- depthwise 7x7 conv: register sliding window, FMA-bound ----------------
__global__ __launch_bounds__(224)
void dwconv7_kernel(const __half* __restrict__ in, const float* __restrict__ w,
                    const float* __restrict__ bias, __half* __restrict__ out, int C)
{
    __shared__ float s_in[20][336];
    __shared__ float s_w[16][49];
    __shared__ float s_b[16];
    __shared__ __align__(16) __half s_out[196][16];

    int nchunk = C >> 4;
    int b  = blockIdx.z / nchunk;
    int c0 = (blockIdx.z % nchunk) << 4;
    int ty0 = blockIdx.y * 14, tx0 = blockIdx.x * 14;
    int tid = threadIdx.x;   // 224

    for (int idx = tid; idx < 800; idx += 224) {
        int p = idx >> 1, h8 = idx & 1;
        int iy = p / 20, ix = p % 20;
        int gy = ty0 + iy - 3, gx = tx0 + ix - 3;
        __half hb[8];
        uint4 z; z.x = z.y = z.z = z.w = 0u;
        *(uint4*)hb = z;
        if (gy >= 0 && gy < HH && gx >= 0 && gx < WW)
            *(uint4*)hb = *(const uint4*)(in + (((size_t)b * HH + gy) * WW + gx) * C + c0 + h8 * 8);
        #pragma unroll
        for (int j = 0; j < 8; j++)
            s_in[iy][ix * 16 + h8 * 8 + j] = __half2float(hb[j]);
    }
    for (int idx = tid; idx < 784; idx += 224)
        s_w[idx / 49][idx % 49] = w[(size_t)(c0 + idx / 49) * 49 + idx % 49];
    if (tid < 16) s_b[tid] = bias[c0 + tid];
    __syncthreads();

    int r = tid >> 4, cc = tid & 15;
    float acc[14];
    #pragma unroll
    for (int x = 0; x < 14; x++) acc[x] = s_b[cc];
    #pragma unroll
    for (int ky = 0; ky < 7; ky++) {
        float wk[7];
        #pragma unroll
        for (int kx = 0; kx < 7; kx++) wk[kx] = s_w[cc][ky * 7 + kx];
        float v[20];
        #pragma unroll
        for (int ix = 0; ix < 20; ix++) v[ix] = s_in[r + ky][ix * 16 + cc];
        #pragma unroll
        for (int kx = 0; kx < 7; kx++)
            #pragma unroll
            for (int x = 0; x < 14; x++) acc[x] += wk[kx] * v[x + kx];
    }
    #pragma unroll
    for (int x = 0; x < 14; x++) s_out[r * 14 + x][cc] = __float2half(acc[x]);
    __syncthreads();

    for (int idx = tid; idx < 392; idx += 224) {
        int p = idx >> 1, h8 = idx & 1;
        int oy = ty0 + p / 14, ox = tx0 + p % 14;
        *(uint4*)(out + (((size_t)b * HH + oy) * WW + ox) * C + c0 + h8 * 8) =
            *(uint4*)&s_out[p][h8 * 8];
    }
}

// ---------------- flash attention, split-K x4 (7 key tiles per CTA) ----------------
#define OM   0
#define OK0  1372
#define OK1  4508
#define OV0  7644
#define OV1  10780
#define OS   13916
#define OMX  19404
#define OSM  19453
#define OSC  19502
#define ATTN_SMEM (19551 * 4)

__global__ __launch_bounds__(256)
void attn_kernel(const float* __restrict__ kvb, const float* __restrict__ m,
                 float* __restrict__ op, float* __restrict__ mxg, float* __restrict__ smg)
{
    extern __shared__ float sm[];
    const int split = blockIdx.x & (NSPLIT - 1);
    const int bh = blockIdx.x >> 2, b = bh >> 3, h = bh & 7;
    const int tid = threadIdx.x, lane = tid & 31, wid = tid >> 5;
    uint32_t sb = smem_u32(sm);

    const float* kbase = kvb + (size_t)b * HW * CC + h * HD2;
    const float* vbase = kbase + C2;
    const int T0 = split * 7;

    for (int idx = tid; idx < 1176; idx += 256) {
        int q = idx / 24, d = idx % 24;
        sm[OM + q * 28 + d] = m[(size_t)bh * 1176 + idx];
    }
    if (tid < 49) { sm[OMX + tid] = -1e30f; sm[OSM + tid] = 0.f; }

    const int pvc = tid & 3, pvg = tid >> 2;
    const int pq0 = (pvg / 8) * 7, pd0 = (pvg % 8) * 3;
    const bool pv_act = (tid < 224);
    float acc[7][3];
    #pragma unroll
    for (int i = 0; i < 7; i++)
        #pragma unroll
        for (int j = 0; j < 3; j++) acc[i][j] = 0.f;

    const int sqb = tid / 28, skb = tid % 28;
    const int sq0 = sqb * 7;
    const bool sc_act = (tid < 196);

    {
        int kt0 = T0 * KT;
        for (int idx = tid; idx < 1344; idx += 256) {
            int mat = idx / 672, r = (idx % 672) / 6, p = idx % 6;
            const float* src = (mat ? vbase : kbase) + (size_t)(kt0 + r) * CC + p * 4;
            uint32_t dst = sb + ((mat ? OV0 : OK0) + r * 28 + p * 4) * 4;
            cp_async16(dst, src);
        }
        cp_commit();
    }

    for (int t = 0; t < 7; t++) {
        int buf = t & 1;
        if (t + 1 < 7) {
            int kt1 = (T0 + t + 1) * KT;
            int nb = buf ^ 1;
            for (int idx = tid; idx < 1344; idx += 256) {
                int mat = idx / 672, r = (idx % 672) / 6, p = idx % 6;
                const float* src = (mat ? vbase : kbase) + (size_t)(kt1 + r) * CC + p * 4;
                uint32_t dst = sb + ((mat ? (nb ? OV1 : OV0) : (nb ? OK1 : OK0)) + r * 28 + p * 4) * 4;
                cp_async16(dst, src);
            }
            cp_commit();
            cp_wait<1>();
        } else {
            cp_wait<0>();
        }
        __syncthreads();

        if (sc_act) {
            const float4* k4 = (const float4*)(sm + (buf ? OK1 : OK0));
            const float4* m4 = (const float4*)(sm + OM);
            float sc[7][4];
            #pragma unroll
            for (int i = 0; i < 7; i++)
                #pragma unroll
                for (int j = 0; j < 4; j++) sc[i][j] = 0.f;
            #pragma unroll
            for (int d4 = 0; d4 < 6; d4++) {
                float4 kv4[4], mm4[7];
                #pragma unroll
                for (int j = 0; j < 4; j++) kv4[j] = k4[(skb + 28 * j) * 7 + d4];
                #pragma unroll
                for (int i = 0; i < 7; i++) mm4[i] = m4[(sq0 + i) * 7 + d4];
                #pragma unroll
                for (int i = 0; i < 7; i++)
                    #pragma unroll
                    for (int j = 0; j < 4; j++)
                        sc[i][j] += mm4[i].x * kv4[j].x + mm4[i].y * kv4[j].y
                                  + mm4[i].z * kv4[j].z + mm4[i].w * kv4[j].w;
            }
            #pragma unroll
            for (int i = 0; i < 7; i++)
                #pragma unroll
                for (int j = 0; j < 4; j++)
                    sm[OS + (sq0 + i) * 112 + skb + 28 * j] = sc[i][j];
        }
        __syncthreads();

        for (int q = wid; q < 49; q += 8) {
            float* row = sm + OS + q * 112;
            float v0 = row[lane], v1 = row[lane + 32], v2 = row[lane + 64];
            float v3 = (lane < 16) ? row[lane + 96] : -1e30f;
            float tmax = fmaxf(fmaxf(v0, v1), fmaxf(v2, v3));
            #pragma unroll
            for (int off = 16; off; off >>= 1)
                tmax = fmaxf(tmax, __shfl_xor_sync(0xffffffffu, tmax, off));
            float mold = sm[OMX + q];
            float mnew = fmaxf(mold, tmax);
            float e0 = expf(v0 - mnew), e1 = expf(v1 - mnew), e2 = expf(v2 - mnew);
            float e3 = (lane < 16) ? expf(v3 - mnew) : 0.f;
            row[lane] = e0; row[lane + 32] = e1; row[lane + 64] = e2;
            if (lane < 16) row[lane + 96] = e3;
            float tsum = e0 + e1 + e2 + e3;
            #pragma unroll
            for (int off = 16; off; off >>= 1)
                tsum += __shfl_xor_sync(0xffffffffu, tsum, off);
            if (lane == 0) {
                float scale = expf(mold - mnew);
                sm[OSC + q] = scale;
                sm[OSM + q] = sm[OSM + q] * scale + tsum;
                sm[OMX + q] = mnew;
            }
        }
        __syncthreads();

        if (pv_act) {
            #pragma unroll
            for (int i = 0; i < 7; i++) {
                float scl = sm[OSC + pq0 + i];
                #pragma unroll
                for (int j = 0; j < 3; j++) acc[i][j] *= scl;
            }
            const float* vb = sm + (buf ? OV1 : OV0);
            for (int lk = 0; lk < 28; lk++) {
                int kk = pvc * 28 + lk;
                float vv0 = vb[kk * 28 + pd0];
                float vv1 = vb[kk * 28 + pd0 + 1];
                float vv2 = vb[kk * 28 + pd0 + 2];
                #pragma unroll
                for (int i = 0; i < 7; i++) {
                    float pp = sm[OS + (pq0 + i) * 112 + kk];
                    acc[i][0] += pp * vv0;
                    acc[i][1] += pp * vv1;
                    acc[i][2] += pp * vv2;
                }
            }
        }
        __syncthreads();
    }

    if (pv_act) {
        #pragma unroll
        for (int i = 0; i < 7; i++)
            #pragma unroll
            for (int j = 0; j < 3; j++)
                sm[OS + ((pq0 + i) * 24 + pd0 + j) * 4 + pvc] = acc[i][j];
    }
    __syncthreads();
    size_t base = (size_t)(bh * NSPLIT + split);
    for (int idx = tid; idx < 1176; idx += 256) {
        float r = sm[OS + idx * 4] + sm[OS + idx * 4 + 1]
                + sm[OS + idx * 4 + 2] + sm[OS + idx * 4 + 3];
        op[base * 1176 + idx] = r;
    }
    if (tid < 49) {
        mxg[base * 49 + tid] = sm[OMX + tid];
        smg[base * 49 + tid] = sm[OSM + tid];
    }
}

// ---------------- attention split merge (log-sum-exp combine) ----------------
__global__ void attn_merge_kernel(const float* __restrict__ op, const float* __restrict__ mxg,
                                  const float* __restrict__ smg, float* __restrict__ o)
{
    __shared__ float wgt[NSPLIT][49];
    __shared__ float den[49];
    int bh = blockIdx.x, tid = threadIdx.x;   // 256 threads
    if (tid < 49) {
        float mx[NSPLIT];
        #pragma unroll
        for (int s = 0; s < NSPLIT; s++) mx[s] = mxg[(size_t)(bh * NSPLIT + s) * 49 + tid];
        float ms = fmaxf(fmaxf(mx[0], mx[1]), fmaxf(mx[2], mx[3]));
        float d = 0.f;
        #pragma unroll
        for (int s = 0; s < NSPLIT; s++) {
            float ww = expf(mx[s] - ms);
            wgt[s][tid] = ww;
            d += smg[(size_t)(bh * NSPLIT + s) * 49 + tid] * ww;
        }
        den[tid] = d;
    }
    __syncthreads();
    for (int idx = tid; idx < 1176; idx += 256) {
        int q = idx / 24;
        float r = 0.f;
        #pragma unroll
        for (int s = 0; s < NSPLIT; s++)
            r += op[(size_t)(bh * NSPLIT + s) * 1176 + idx] * wgt[s][q];
        o[(size_t)bh * 1176 + idx] = r / den[q];
    }
}

// ---------------- concat [q*a | bilinear(o) | cut*xe2], fused upsample ----------------
__global__ void cat_kernel(const __half* __restrict__ q, const __half* __restrict__ a,
                           const float* __restrict__ o, const __half* __restrict__ cut,
                           const __half* __restrict__ xe2, __half* __restrict__ cat)
{
    size_t row = blockIdx.x;
    int t = threadIdx.x;                 // 192 threads, 4 halves each
    __half v[4];
    if (t < 96) {
        int c = t * 4;
        #pragma unroll
        for (int j = 0; j < 4; j++)
            v[j] = __float2half(__half2float(q[row * 384 + c + j]) *
                                __half2float(a[row * 384 + c + j]));
    } else if (t < 144) {
        int c = (t - 96) * 4;
        int b = (int)(row / HW); int rem = (int)(row % HW);
        int y = rem / WW, x = rem % WW;
        int h = c / HD2, d = c % HD2;
        float fy = (y + 0.5f) * 0.125f - 0.5f;
        float fx = (x + 0.5f) * 0.125f - 0.5f;
        int y0 = (int)floorf(fy); float ty = fy - (float)y0;
        int x0 = (int)floorf(fx); float tx = fx - (float)x0;
        int y0c = max(y0, 0), y1c = min(y0 + 1, 6);
        int x0c = max(x0, 0), x1c = min(x0 + 1, 6);
        const float* ob = o + ((size_t)(b * NHD + h) * 49) * HD2 + d;
        float4 v00 = *(const float4*)(ob + (y0c * 7 + x0c) * HD2);
        float4 v01 = *(const float4*)(ob + (y0c * 7 + x1c) * HD2);
        float4 v10 = *(const float4*)(ob + (y1c * 7 + x0c) * HD2);
        float4 v11 = *(const float4*)(ob + (y1c * 7 + x1c) * HD2);
        float w00 = (1.f - ty) * (1.f - tx), w01 = (1.f - ty) * tx;
        float w10 = ty * (1.f - tx), w11 = ty * tx;
        v[0] = __float2half(w00 * v00.x + w01 * v01.x + w10 * v10.x + w11 * v11.x);
        v[1] = __float2half(w00 * v00.y + w01 * v01.y + w10 * v10.y + w11 * v11.y);
        v[2] = __float2half(w00 * v00.z + w01 * v01.z + w10 * v10.z + w11 * v11.z);
        v[3] = __float2half(w00 * v00.w + w01 * v01.w + w10 * v10.w + w11 * v11.w);
    } else {
        int c = (t - 144) * 4;
        #pragma unroll
        for (int j = 0; j < 4; j++)
            v[j] = __float2half(__half2float(cut[row * 192 + c + j]) *
                                __half2float(xe2[row * 192 + c + j]));
    }
    *(uint2*)(cat + row * 768 + t * 4) = *(uint2*)v;
}

// ---------------- launch ----------------
extern "C" void kernel_launch(void* const* d_in, const int* in_sizes, int n_in,
                              void* d_out, int out_size)
{
    const float* x       = (const float*)d_in[0];
    const float* x_e     = (const float*)d_in[1];
    const float* norm_w  = (const float*)d_in[2];
    const float* norm_b  = (const float*)d_in[3];
    const float* norme_w = (const float*)d_in[4];
    const float* norme_b = (const float*)d_in[5];
    const float* q_w     = (const float*)d_in[6];
    const float* q_b     = (const float*)d_in[7];
    const float* qcut_w  = (const float*)d_in[8];
    const float* qcut_b  = (const float*)d_in[9];
    const float* a_w     = (const float*)d_in[10];
    const float* a_b     = (const float*)d_in[11];
    const float* l_w     = (const float*)d_in[12];
    const float* l_b     = (const float*)d_in[13];
    const float* conv_w  = (const float*)d_in[14];
    const float* conv_b  = (const float*)d_in[15];
    const float* econv_w = (const float*)d_in[16];
    const float* econv_b = (const float*)d_in[17];
    const float* efore_w = (const float*)d_in[18];
    const float* efore_b = (const float*)d_in[19];
    const float* eback_w = (const float*)d_in[20];
    const float* eback_b = (const float*)d_in[21];
    const float* kv_w    = (const float*)d_in[22];
    const float* kv_b    = (const float*)d_in[23];
    const float* scl_w   = (const float*)d_in[24];
    const float* scl_b   = (const float*)d_in[25];
    const float* proj_w  = (const float*)d_in[26];
    const float* proj_b  = (const float*)d_in[27];
    const float* proje_w = (const float*)d_in[28];
    const float* proje_b = (const float*)d_in[29];
    float* out = (float*)d_out;
    float* out_x  = out;
    float* out_xe = out + (size_t)MM * CC;

    __half *xn,*xen,*qb,*cutb,*lx,*clx,*ab,*ef,*efc,*xe2,*catb;
    __half *w3,*w2,*tkv,*ta,*tefore,*teback;
    float *b3,*b2,*kvb,*mb,*ob,*opb,*mxb,*smb;
    cudaGetSymbolAddress((void**)&xn,   g_xn);
    cudaGetSymbolAddress((void**)&xen,  g_xen);
    cudaGetSymbolAddress((void**)&qb,   g_q);
    cudaGetSymbolAddress((void**)&cutb, g_cut);
    cudaGetSymbolAddress((void**)&lx,   g_lx);
    cudaGetSymbolAddress((void**)&clx,  g_clx);
    cudaGetSymbolAddress((void**)&ab,   g_a);
    cudaGetSymbolAddress((void**)&kvb,  g_kv);
    cudaGetSymbolAddress((void**)&ef,   g_ef);
    cudaGetSymbolAddress((void**)&efc,  g_efc);
    cudaGetSymbolAddress((void**)&xe2,  g_xe2);
    cudaGetSymbolAddress((void**)&mb,   g_m);
    cudaGetSymbolAddress((void**)&ob,   g_o);
    cudaGetSymbolAddress((void**)&opb,  g_op);
    cudaGetSymbolAddress((void**)&mxb,  g_mx);
    cudaGetSymbolAddress((void**)&smb,  g_sm2);
    cudaGetSymbolAddress((void**)&catb, g_cat);
    cudaGetSymbolAddress((void**)&w3,     g_w3);
    cudaGetSymbolAddress((void**)&b3,     g_b3);
    cudaGetSymbolAddress((void**)&w2,     g_w2);
    cudaGetSymbolAddress((void**)&b2,     g_b2);
    cudaGetSymbolAddress((void**)&tkv,    g_tkv);
    cudaGetSymbolAddress((void**)&ta,     g_ta);
    cudaGetSymbolAddress((void**)&tefore, g_tefore);
    cudaGetSymbolAddress((void**)&teback, g_teback);

    cudaFuncSetAttribute(h16_gemm_kernel, cudaFuncAttributeMaxDynamicSharedMemorySize, GEMM_SMEM);
    cudaFuncSetAttribute(h16_gemm_routed, cudaFuncAttributeMaxDynamicSharedMemorySize, GEMM_SMEM);
    cudaFuncSetAttribute(attn_kernel, cudaFuncAttributeMaxDynamicSharedMemorySize, ATTN_SMEM);

    // 0) all weight transposes + bias concat in one launch
    transpose_all_kernel<<<4999, 256>>>(q_w, l_w, a_w, kv_w, qcut_w, efore_w, eback_w,
                                        proj_w, proje_w,
                                        q_b, l_b, qcut_b, proj_b, proje_b,
                                        w3, b3, w2, b2, tkv, ta, tefore, teback);

    // 1) both LayerNorms in one launch
    ln_kernel<<<LN_BLOCKS_X + MM / 8, 256>>>(x, norm_w, norm_b, xn,
                                             x_e, norme_w, norme_b, xen);

    // 2) pooled shortcut queries -> m (scaled, fp32)
    pool_scl_kernel<<<BB * 49, 192>>>(xn, xen, scl_w, scl_b, mb);

    // 3) fused q + lx(gelu) + cut GEMM (one launch, shared A = xn)
    h16_gemm_routed<<<dim3(8, MM / 128), 256, GEMM_SMEM>>>(
        xn, w3, b3, qb, lx, cutb, nullptr, nullptr, 1024, 384, 0);

    // 4) depthwise conv on lx, then a / kv GEMMs (kv -> fp32 for attention)
    dim3 gN384(3, MM / 128), gN192(2, MM / 128);
    dwconv7_kernel<<<dim3(4, 4, BB * (CC / 16)), 224>>>(lx, conv_w, conv_b, clx, CC);
    h16_gemm_kernel<<<gN384, 256, GEMM_SMEM>>>(clx, ta,  a_b,  nullptr, ab, 384, 384);
    h16_gemm_kernel<<<gN384, 256, GEMM_SMEM>>>(lx,  tkv, kv_b, kvb, nullptr, 384, 384);

    // 5) flash attention (split-K x4) + merge
    attn_kernel<<<BB * NHD * NSPLIT, 256, ATTN_SMEM>>>(kvb, mb, opb, mxb, smb);
    attn_merge_kernel<<<BB * NHD, 256>>>(opb, mxb, smb, ob);

    // 6) x_e depthwise branch
    h16_gemm_kernel<<<gN192, 256, GEMM_SMEM>>>(xen, tefore, efore_b, nullptr, ef, 192, 192);
    dwconv7_kernel<<<dim3(4, 4, BB * (C2 / 16)), 224>>>(ef, econv_w, econv_b, efc, C2);
    h16_gemm_kernel<<<gN192, 256, GEMM_SMEM>>>(efc, teback, eback_b, nullptr, xe2, 192, 192);

    // 7) concat (fused bilinear upsample) + fused proj/proje GEMM (fp32 out)
    cat_kernel<<<MM, 192>>>(qb, ab, ob, cutb, xe2, catb);
    h16_gemm_routed<<<dim3(5, MM / 128), 256, GEMM_SMEM>>>(
        catb, w2, b2, nullptr, nullptr, nullptr, out_x, out_xe, 640, 768, 1);
}

// round 13
// speedup vs baseline: 1.1507x; 1.0069x over previous
#include <cuda_runtime.h>
#include <cuda_fp16.h>
#include <math.h>
#include <stdint.h>

// ---------------- problem constants ----------------
#define BB   16
#define HH   56
#define WW   56
#define CC   384
#define C2   192
#define NHD  8
#define HD2  24
#define MM   (BB*HH*WW)        // 50176 tokens
#define HW   (HH*WW)           // 3136
#define KT   112               // attn key tile: 3136 = 28*112
#define NSPLIT 4               // attention kv splits (7 tiles each)
#define SCALE_F 0.20412414523193154f

// ---------------- scratch (device globals; no allocation allowed) ----------------
__device__ __align__(16) __half g_xn  [(size_t)MM*CC];
__device__ __align__(16) __half g_xen [(size_t)MM*C2];
__device__ __align__(16) __half g_q   [(size_t)MM*CC];
__device__ __align__(16) __half g_cut [(size_t)MM*C2];
__device__ __align__(16) __half g_lx  [(size_t)MM*CC];
__device__ __align__(16) __half g_clx [(size_t)MM*CC];
__device__ __align__(16) float  g_kv  [(size_t)MM*CC];    // attn input stays fp32
__device__ __align__(16) __half g_ef  [(size_t)MM*C2];
__device__ __align__(16) __half g_efc [(size_t)MM*C2];
__device__ __align__(16) float  g_m   [(size_t)BB*NHD*49*HD2];
__device__ __align__(16) float  g_o   [(size_t)BB*NHD*49*HD2];
__device__ __align__(16) float  g_op  [(size_t)BB*NHD*NSPLIT*49*HD2];
__device__ __align__(16) float  g_mx  [(size_t)BB*NHD*NSPLIT*49];
__device__ __align__(16) float  g_sm2 [(size_t)BB*NHD*NSPLIT*49];
__device__ __align__(16) __half g_cat [(size_t)MM*768];

// fused transposed weights (fp16) + biases (fp32)
__device__ __align__(16) __half g_w3 [1024*384];   // [q | l | qcut(pad 256)] rows, K=384
__device__ __align__(16) float  g_b3 [1024];
__device__ __align__(16) __half g_w2 [640*768];    // [proj | proje(pad)] rows, K=768
__device__ __align__(16) float  g_b2 [640];
__device__ __align__(16) __half g_tkv   [384*384];
__device__ __align__(16) __half g_ta    [384*384];
__device__ __align__(16) __half g_tefore[256*192];
__device__ __align__(16) __half g_teback[256*192];

// ---------------- PTX helpers (sm_80+ features only; no 'a'-gated instrs) ----------------
__device__ __forceinline__ uint32_t smem_u32(const void* p) {
    uint32_t r;
    asm("{ .reg .u64 t; cvta.to.shared.u64 t, %1; cvt.u32.u64 %0, t; }" : "=r"(r) : "l"(p));
    return r;
}
__device__ __forceinline__ void cp_async16(uint32_t dst, const void* src) {
    asm volatile("cp.async.ca.shared.global [%0], [%1], 16;" :: "r"(dst), "l"(src) : "memory");
}
__device__ __forceinline__ void cp_commit() {
    asm volatile("cp.async.commit_group;" ::: "memory");
}
template<int N>
__device__ __forceinline__ void cp_wait() {
    asm volatile("cp.async.wait_group %0;" :: "n"(N) : "memory");
}
__device__ __forceinline__ void ldsm_x4(uint32_t& r0, uint32_t& r1, uint32_t& r2, uint32_t& r3,
                                        uint32_t addr) {
    asm volatile("ldmatrix.sync.aligned.m8n8.x4.shared.b16 {%0,%1,%2,%3}, [%4];"
                 : "=r"(r0), "=r"(r1), "=r"(r2), "=r"(r3) : "r"(addr));
}
__device__ __forceinline__ void mma_f16(float* c, const uint32_t* a, uint32_t b0, uint32_t b1) {
    asm volatile(
        "mma.sync.aligned.m16n8k16.row.col.f32.f16.f16.f32 "
        "{%0,%1,%2,%3}, {%4,%5,%6,%7}, {%8,%9}, {%0,%1,%2,%3};"
        : "+f"(c[0]), "+f"(c[1]), "+f"(c[2]), "+f"(c[3])
        : "r"(a[0]), "r"(a[1]), "r"(a[2]), "r"(a[3]), "r"(b0), "r"(b1));
}
__device__ __forceinline__ float gelu_f(float v) {
    return 0.5f * v * (1.f + erff(v * 0.70710678118654752f));
}

// ---------------- batched weight transpose + pad + fp16 + bias concat (one launch) ----------------
__global__ void transpose_all_kernel(
    const float* __restrict__ q_w,     const float* __restrict__ l_w,
    const float* __restrict__ a_w,     const float* __restrict__ kv_w,
    const float* __restrict__ qcut_w,  const float* __restrict__ efore_w,
    const float* __restrict__ eback_w, const float* __restrict__ proj_w,
    const float* __restrict__ proje_w,
    const float* __restrict__ q_b,     const float* __restrict__ l_b,
    const float* __restrict__ qcut_b,  const float* __restrict__ proj_b,
    const float* __restrict__ proje_b,
    __half* __restrict__ w3, float* __restrict__ b3,
    __half* __restrict__ w2, float* __restrict__ b2,
    __half* __restrict__ tkv, __half* __restrict__ ta,
    __half* __restrict__ tefore, __half* __restrict__ teback)
{
    int idx = blockIdx.x * 256 + threadIdx.x;   // grid 4999 covers 1279616
    if (idx < 393216) {                         // w3 [1024 x 384]
        int n = idx / 384, k = idx % 384;
        float v;
        if      (n <  384) v = q_w[(size_t)k * 384 + n];
        else if (n <  768) v = l_w[(size_t)k * 384 + (n - 384)];
        else if (n <  960) v = qcut_w[(size_t)k * 192 + (n - 768)];
        else               v = 0.f;
        w3[idx] = __float2half(v);
    } else if (idx < 884736) {                  // w2 [640 x 768]
        int off = idx - 393216;
        int n = off / 768, k = off % 768;
        float v;
        if      (n < 384) v = proj_w[(size_t)k * 384 + n];
        else if (n < 576) v = proje_w[(size_t)k * 192 + (n - 384)];
        else              v = 0.f;
        w2[off] = __float2half(v);
    } else if (idx < 1032192) {                 // tkv
        int off = idx - 884736;
        int n = off / 384, k = off % 384;
        tkv[off] = __float2half(kv_w[(size_t)k * 384 + n]);
    } else if (idx < 1179648) {                 // ta
        int off = idx - 1032192;
        int n = off / 384, k = off % 384;
        ta[off] = __float2half(a_w[(size_t)k * 384 + n]);
    } else if (idx < 1228800) {                 // tefore [256 x 192]
        int off = idx - 1179648;
        int n = off / 192, k = off % 192;
        tefore[off] = __float2half((n < 192) ? efore_w[(size_t)k * 192 + n] : 0.f);
    } else if (idx < 1277952) {                 // teback [256 x 192]
        int off = idx - 1228800;
        int n = off / 192, k = off % 192;
        teback[off] = __float2half((n < 192) ? eback_w[(size_t)k * 192 + n] : 0.f);
    } else if (idx < 1278976) {                 // b3 [1024]
        int j = idx - 1277952;
        float v;
        if      (j <  384) v = q_b[j];
        else if (j <  768) v = l_b[j - 384];
        else if (j <  960) v = qcut_b[j - 768];
        else               v = 0.f;
        b3[j] = v;
    } else if (idx < 1279616) {                 // b2 [640]
        int j = idx - 1278976;
        float v;
        if      (j < 384) v = proj_b[j];
        else if (j < 576) v = proje_b[j - 384];
        else              v = 0.f;
        b2[j] = v;
    }
}

// ================= GEMM pipeline core (round-8 proven: 2-stage, 2 syncs/chunk) =================
#define SSH 72
#define STAGE_BYTES (128 * SSH * 2 * 2)     // A+B per stage = 36864 B
#define GEMM_SMEM (2 * STAGE_BYTES)         // 73728 B
#define GEMM_PIPE_BODY                                                                   \
    float acc[2][8][4];                                                                  \
    _Pragma("unroll")                                                                    \
    for (int i = 0; i < 2; i++)                                                          \
        _Pragma("unroll")                                                                \
        for (int j = 0; j < 8; j++)                                                      \
            _Pragma("unroll")                                                            \
            for (int t = 0; t < 4; t++) acc[i][j][t] = 0.f;                              \
    const int NC = K >> 6;                                                               \
    const uint32_t aoff = (uint32_t)((lane & 7) + ((lane >> 3) & 1) * 8) * 144 + (lane >> 4) * 16; \
    const uint32_t boff = (uint32_t)((lane & 7) + (lane >> 4) * 8) * 144 + ((lane >> 3) & 1) * 16; \
    _Pragma("unroll")                                                                    \
    for (int it = 0; it < 4; it++) {                                                     \
        int row = ldrow + it * 32;                                                       \
        uint32_t o = (uint32_t)row * 144 + ldch * 16;                                    \
        cp_async16(sb + o, Ab + (size_t)row * K + ldch * 8);                             \
        cp_async16(sb + 128 * SSH * 2 + o, Bb + (size_t)row * K + ldch * 8);             \
    }                                                                                    \
    cp_commit();                                                                         \
    for (int c = 0; c < NC; c++) {                                                       \
        int buf = c & 1;                                                                 \
        if (c + 1 < NC) {                                                                \
            uint32_t stage = sb + (uint32_t)((c + 1) & 1) * STAGE_BYTES;                 \
            const __half* ga = Ab + (c + 1) * 64;                                        \
            const __half* gb = Bb + (c + 1) * 64;                                        \
            _Pragma("unroll")                                                            \
            for (int it = 0; it < 4; it++) {                                             \
                int row = ldrow + it * 32;                                               \
                uint32_t o = (uint32_t)row * 144 + ldch * 16;                            \
                cp_async16(stage + o, ga + (size_t)row * K + ldch * 8);                  \
                cp_async16(stage + 128 * SSH * 2 + o, gb + (size_t)row * K + ldch * 8);  \
            }                                                                            \
            cp_commit();                                                                 \
            cp_wait<1>();                                                                \
        } else {                                                                         \
            cp_wait<0>();                                                                \
        }                                                                                \
        __syncthreads();                                                                 \
        uint32_t sA  = sb + (uint32_t)buf * STAGE_BYTES + (uint32_t)warpM * 144 + aoff;  \
        uint32_t sBv = sb + (uint32_t)buf * STAGE_BYTES + 128 * SSH * 2 + (uint32_t)warpN * 144 + boff; \
        _Pragma("unroll")                                                                \
        for (int ks = 0; ks < 4; ks++) {                                                 \
            uint32_t afr[2][4];                                                          \
            ldsm_x4(afr[0][0], afr[0][1], afr[0][2], afr[0][3], sA + ks * 32);           \
            ldsm_x4(afr[1][0], afr[1][1], afr[1][2], afr[1][3], sA + 16 * 144 + ks * 32);\
            _Pragma("unroll")                                                            \
            for (int ntp = 0; ntp < 4; ntp++) {                                          \
                uint32_t b0, b1, b2, b3;                                                 \
                ldsm_x4(b0, b1, b2, b3, sBv + (uint32_t)ntp * 16 * 144 + ks * 32);       \
                mma_f16(acc[0][ntp * 2],     afr[0], b0, b1);                            \
                mma_f16(acc[1][ntp * 2],     afr[1], b0, b1);                            \
                mma_f16(acc[0][ntp * 2 + 1], afr[0], b2, b3);                            \
                mma_f16(acc[1][ntp * 2 + 1], afr[1], b2, b3);                            \
            }                                                                            \
        }                                                                                \
        __syncthreads();                                                                 \
    }

// ---------------- generic fp16 GEMM: C = A @ Bt^T + bias (half or float out) ----------------
__global__ __launch_bounds__(256, 2)
void h16_gemm_kernel(const __half* __restrict__ A, const __half* __restrict__ Bt,
                     const float* __restrict__ bias, float* __restrict__ Cf,
                     __half* __restrict__ Ch, int N, int K)
{
    extern __shared__ __half smh[];
    const int tid = threadIdx.x, lane = tid & 31, wid = tid >> 5;
    const int bn = blockIdx.x, bm = blockIdx.y;
    const int warpM = (wid & 3) * 32, warpN = (wid >> 2) * 64;
    const __half* Ab = A  + (size_t)bm * 128 * K;
    const __half* Bb = Bt + (size_t)bn * 128 * K;
    uint32_t sb = smem_u32(smh);
    const int ldrow = tid >> 3;
    const int ldch  = tid & 7;

    GEMM_PIPE_BODY

    #pragma unroll
    for (int mt = 0; mt < 2; mt++) {
        size_t row0 = (size_t)bm * 128 + warpM + mt * 16 + (lane >> 2);
        #pragma unroll
        for (int nt = 0; nt < 8; nt++) {
            int gcol = bn * 128 + warpN + nt * 8 + (lane & 3) * 2;
            if (gcol < N) {
                float bs0 = bias[gcol], bs1 = bias[gcol + 1];
                float v0 = acc[mt][nt][0] + bs0;
                float v1 = acc[mt][nt][1] + bs1;
                float v2 = acc[mt][nt][2] + bs0;
                float v3 = acc[mt][nt][3] + bs1;
                if (Ch) {
                    __half2 h0; h0.x = __float2half(v0); h0.y = __float2half(v1);
                    __half2 h1; h1.x = __float2half(v2); h1.y = __float2half(v3);
                    *(__half2*)(Ch + row0 * (size_t)N + gcol) = h0;
                    *(__half2*)(Ch + (row0 + 8) * (size_t)N + gcol) = h1;
                } else {
                    float2 p0; p0.x = v0; p0.y = v1;
                    float2 p1; p1.x = v2; p1.y = v3;
                    *(float2*)(Cf + row0 * (size_t)N + gcol) = p0;
                    *(float2*)(Cf + (row0 + 8) * (size_t)N + gcol) = p1;
                }
            }
        }
    }
}

// ---------------- routed fp16 GEMM: fused multi-output / multiplied epilogues ----------------
// mode 0 (N=1024, A=xn):  col<384 -> o0 (q); col<768 -> o1 (lx, gelu); col<960 -> o2 (cut)
// mode 1 (N=640,  A=cat): col<384 -> f0 (out_x, fp32); col<576 -> f1 (out_xe, fp32)
// mode 2 (N=384,  A=clx): cat[:,col] = (acc+bias) * mul[row,col]   (mul ld 384, cat ld 768)
// mode 3 (N=256,  A=efc): col<192: cat[:,576+col] = (acc+bias) * mul[row,col] (mul ld 192)
__global__ __launch_bounds__(256, 2)
void h16_gemm_routed(const __half* __restrict__ A, const __half* __restrict__ Bt,
                     const float* __restrict__ bias, const __half* __restrict__ mul,
                     __half* __restrict__ o0, __half* __restrict__ o1, __half* __restrict__ o2,
                     float* __restrict__ f0, float* __restrict__ f1,
                     int N, int K, int mode)
{
    extern __shared__ __half smh[];
    const int tid = threadIdx.x, lane = tid & 31, wid = tid >> 5;
    const int bn = blockIdx.x, bm = blockIdx.y;
    const int warpM = (wid & 3) * 32, warpN = (wid >> 2) * 64;
    const __half* Ab = A  + (size_t)bm * 128 * K;
    const __half* Bb = Bt + (size_t)bn * 128 * K;
    uint32_t sb = smem_u32(smh);
    const int ldrow = tid >> 3;
    const int ldch  = tid & 7;

    GEMM_PIPE_BODY

    #pragma unroll
    for (int mt = 0; mt < 2; mt++) {
        size_t row0 = (size_t)bm * 128 + warpM + mt * 16 + (lane >> 2);
        #pragma unroll
        for (int nt = 0; nt < 8; nt++) {
            int gcol = bn * 128 + warpN + nt * 8 + (lane & 3) * 2;
            float bs0 = bias[gcol], bs1 = bias[gcol + 1];
            float v0 = acc[mt][nt][0] + bs0;
            float v1 = acc[mt][nt][1] + bs1;
            float v2 = acc[mt][nt][2] + bs0;
            float v3 = acc[mt][nt][3] + bs1;
            if (mode == 0) {
                __half* dst; int col, ldc;
                if (gcol < 384)      { dst = o0; col = gcol;       ldc = 384; }
                else if (gcol < 768) { dst = o1; col = gcol - 384; ldc = 384;
                                       v0 = gelu_f(v0); v1 = gelu_f(v1);
                                       v2 = gelu_f(v2); v3 = gelu_f(v3); }
                else if (gcol < 960) { dst = o2; col = gcol - 768; ldc = 192; }
                else continue;
                __half2 h0; h0.x = __float2half(v0); h0.y = __float2half(v1);
                __half2 h1; h1.x = __float2half(v2); h1.y = __float2half(v3);
                *(__half2*)(dst + row0 * (size_t)ldc + col) = h0;
                *(__half2*)(dst + (row0 + 8) * (size_t)ldc + col) = h1;
            } else if (mode == 1) {
                float* dst; int col, ldc;
                if (gcol < 384)      { dst = f0; col = gcol;       ldc = 384; }
                else if (gcol < 576) { dst = f1; col = gcol - 384; ldc = 192; }
                else continue;
                float2 p0; p0.x = v0; p0.y = v1;
                float2 p1; p1.x = v2; p1.y = v3;
                *(float2*)(dst + row0 * (size_t)ldc + col) = p0;
                *(float2*)(dst + (row0 + 8) * (size_t)ldc + col) = p1;
            } else if (mode == 2) {       // cat[:,0:384] = (acc+bias) * q
                __half2 m0 = *(const __half2*)(mul + row0 * 384 + gcol);
                __half2 m1 = *(const __half2*)(mul + (row0 + 8) * 384 + gcol);
                __half2 h0; h0.x = __float2half(v0 * __half2float(m0.x));
                            h0.y = __float2half(v1 * __half2float(m0.y));
                __half2 h1; h1.x = __float2half(v2 * __half2float(m1.x));
                            h1.y = __float2half(v3 * __half2float(m1.y));
                *(__half2*)(o0 + row0 * 768 + gcol) = h0;
                *(__half2*)(o0 + (row0 + 8) * 768 + gcol) = h1;
            } else {                      // mode 3: cat[:,576:768] = (acc+bias) * cut
                if (gcol < 192) {
                    __half2 m0 = *(const __half2*)(mul + row0 * 192 + gcol);
                    __half2 m1 = *(const __half2*)(mul + (row0 + 8) * 192 + gcol);
                    __half2 h0; h0.x = __float2half(v0 * __half2float(m0.x));
                                h0.y = __float2half(v1 * __half2float(m0.y));
                    __half2 h1; h1.x = __float2half(v2 * __half2float(m1.x));
                                h1.y = __float2half(v3 * __half2float(m1.y));
                    *(__half2*)(o0 + row0 * 768 + 576 + gcol) = h0;
                    *(__half2*)(o0 + (row0 + 8) * 768 + 576 + gcol) = h1;
                }
            }
        }
    }
}

// ---------------- LayerNorm: one warp per row, both tensors in one launch ----------------
#define LN_BLOCKS_X (MM / 8)
__global__ void ln_kernel(const float* __restrict__ x, const float* __restrict__ w,
                          const float* __restrict__ b, __half* __restrict__ out,
                          const float* __restrict__ xe, const float* __restrict__ we,
                          const float* __restrict__ be, __half* __restrict__ oute)
{
    int blk = blockIdx.x;
    const float* xx; const float* ww; const float* bb; __half* oo; int C;
    if (blk < LN_BLOCKS_X) { xx = x;  ww = w;  bb = b;  oo = out;  C = CC; }
    else                   { xx = xe; ww = we; bb = be; oo = oute; C = C2; blk -= LN_BLOCKS_X; }
    int row = blk * 8 + (threadIdx.x >> 5);
    int lane = threadIdx.x & 31;
    const float* xr = xx + (size_t)row * C;
    __half* orow = oo + (size_t)row * C;

    int n = C >> 5;
    float local[12];
    float s = 0.f;
    for (int i = 0; i < n; i++) { float v = xr[lane + 32 * i]; local[i] = v; s += v; }
    #pragma unroll
    for (int o = 16; o; o >>= 1) s += __shfl_xor_sync(0xffffffffu, s, o);
    float mean = s / (float)C;

    float ss = 0.f;
    for (int i = 0; i < n; i++) { float d = local[i] - mean; ss += d * d; }
    #pragma unroll
    for (int o = 16; o; o >>= 1) ss += __shfl_xor_sync(0xffffffffu, ss, o);
    float rstd = rsqrtf(ss / (float)C + 1e-6f);

    for (int i = 0; i < n; i++) {
        int cidx = lane + 32 * i;
        orow[cidx] = __float2half((local[i] - mean) * rstd * ww[cidx] + bb[cidx]);
    }
}

// ---------------- pooled shortcut queries + scl GEMM + SCALE fold (half2 loads) ----------------
__global__ void pool_scl_kernel(const __half* __restrict__ xn, const __half* __restrict__ xen,
                                const float* __restrict__ sw, const float* __restrict__ sb,
                                float* __restrict__ mout)
{
    __shared__ float pooled[576];
    int blk = blockIdx.x; int b = blk / 49, qi = blk % 49;
    int py = qi / 7, px = qi % 7;
    int tid = threadIdx.x;    // 192 threads

    for (int ch2 = tid; ch2 < 288; ch2 += 192) {
        float sx = 0.f, sy = 0.f;
        if (ch2 < 192) {
            const __half2* base = (const __half2*)(xn + ((size_t)(b * HH + py * 8) * WW + px * 8) * CC) + ch2;
            #pragma unroll
            for (int hy = 0; hy < 8; hy++)
                #pragma unroll
                for (int wx = 0; wx < 8; wx++) {
                    float2 v = __half22float2(base[(size_t)(hy * WW + wx) * 192]);
                    sx += v.x; sy += v.y;
                }
        } else {
            const __half2* base = (const __half2*)(xen + ((size_t)(b * HH + py * 8) * WW + px * 8) * C2) + (ch2 - 192);
            #pragma unroll
            for (int hy = 0; hy < 8; hy++)
                #pragma unroll
                for (int wx = 0; wx < 8; wx++) {
                    float2 v = __half22float2(base[(size_t)(hy * WW + wx) * 96]);
                    sx += v.x; sy += v.y;
                }
        }
        pooled[ch2 * 2]     = sx * (1.0f / 64.0f);
        pooled[ch2 * 2 + 1] = sy * (1.0f / 64.0f);
    }
    __syncthreads();

    int j = tid;
    float a = sb[j];
    for (int kk = 0; kk < 576; kk++) a += pooled[kk] * sw[(size_t)kk * C2 + j];
    a *= SCALE_F;
    mout[((size_t)(b * NHD + j / HD2) * 49 + qi) * HD2 + (j % HD2)] = a;
}

// ---------------- depthwise 7x7 conv: register sliding window, FMA-bound ----------------
__global__ __launch_bounds__(224)
void dwconv7_kernel(const __half* __restrict__ in, const float* __restrict__ w,
                    const float* __restrict__ bias, __half* __restrict__ out, int C)
{
    __shared__ float s_in[20][336];
    __shared__ float s_w[16][49];
    __shared__ float s_b[16];
    __shared__ __align__(16) __half s_out[196][16];

    int nchunk = C >> 4;
    int b  = blockIdx.z / nchunk;
    int c0 = (blockIdx.z % nchunk) << 4;
    int ty0 = blockIdx.y * 14, tx0 = blockIdx.x * 14;
    int tid = threadIdx.x;   // 224

    for (int idx = tid; idx < 800; idx += 224) {
        int p = idx >> 1, h8 = idx & 1;
        int iy = p / 20, ix = p % 20;
        int gy = ty0 + iy - 3, gx = tx0 + ix - 3;
        __half hb[8];
        uint4 z; z.x = z.y = z.z = z.w = 0u;
        *(uint4*)hb = z;
        if (gy >= 0 && gy < HH && gx >= 0 && gx < WW)
            *(uint4*)hb = *(const uint4*)(in + (((size_t)b * HH + gy) * WW + gx) * C + c0 + h8 * 8);
        #pragma unroll
        for (int j = 0; j < 8; j++)
            s_in[iy][ix * 16 + h8 * 8 + j] = __half2float(hb[j]);
    }
    for (int idx = tid; idx < 784; idx += 224)
        s_w[idx / 49][idx % 49] = w[(size_t)(c0 + idx / 49) * 49 + idx % 49];
    if (tid < 16) s_b[tid] = bias[c0 + tid];
    __syncthreads();

    int r = tid >> 4, cc = tid & 15;
    float acc[14];
    #pragma unroll
    for (int x = 0; x < 14; x++) acc[x] = s_b[cc];
    #pragma unroll
    for (int ky = 0; ky < 7; ky++) {
        float wk[7];
        #pragma unroll
        for (int kx = 0; kx < 7; kx++) wk[kx] = s_w[cc][ky * 7 + kx];
        float v[20];
        #pragma unroll
        for (int ix = 0; ix < 20; ix++) v[ix] = s_in[r + ky][ix * 16 + cc];
        #pragma unroll
        for (int kx = 0; kx < 7; kx++)
            #pragma unroll
            for (int x = 0; x < 14; x++) acc[x] += wk[kx] * v[x + kx];
    }
    #pragma unroll
    for (int x = 0; x < 14; x++) s_out[r * 14 + x][cc] = __float2half(acc[x]);
    __syncthreads();

    for (int idx = tid; idx < 392; idx += 224) {
        int p = idx >> 1, h8 = idx & 1;
        int oy = ty0 + p / 14, ox = tx0 + p % 14;
        *(uint4*)(out + (((size_t)b * HH + oy) * WW + ox) * C + c0 + h8 * 8) =
            *(uint4*)&s_out[p][h8 * 8];
    }
}

// ---------------- flash attention, split-K x4 (7 key tiles per CTA) ----------------
#define OM   0
#define OK0  1372
#define OK1  4508
#define OV0  7644
#define OV1  10780
#define OS   13916
#define OMX  19404
#define OSM  19453
#define OSC  19502
#define ATTN_SMEM (19551 * 4)

__global__ __launch_bounds__(256)
void attn_kernel(const float* __restrict__ kvb, const float* __restrict__ m,
                 float* __restrict__ op, float* __restrict__ mxg, float* __restrict__ smg)
{
    extern __shared__ float sm[];
    const int split = blockIdx.x & (NSPLIT - 1);
    const int bh = blockIdx.x >> 2, b = bh >> 3, h = bh & 7;
    const int tid = threadIdx.x, lane = tid & 31, wid = tid >> 5;
    uint32_t sb = smem_u32(sm);

    const float* kbase = kvb + (size_t)b * HW * CC + h * HD2;
    const float* vbase = kbase + C2;
    const int T0 = split * 7;

    for (int idx = tid; idx < 1176; idx += 256) {
        int q = idx / 24, d = idx % 24;
        sm[OM + q * 28 + d] = m[(size_t)bh * 1176 + idx];
    }
    if (tid < 49) { sm[OMX + tid] = -1e30f; sm[OSM + tid] = 0.f; }

    const int pvc = tid & 3, pvg = tid >> 2;
    const int pq0 = (pvg / 8) * 7, pd0 = (pvg % 8) * 3;
    const bool pv_act = (tid < 224);
    float acc[7][3];
    #pragma unroll
    for (int i = 0; i < 7; i++)
        #pragma unroll
        for (int j = 0; j < 3; j++) acc[i][j] = 0.f;

    const int sqb = tid / 28, skb = tid % 28;
    const int sq0 = sqb * 7;
    const bool sc_act = (tid < 196);

    {
        int kt0 = T0 * KT;
        for (int idx = tid; idx < 1344; idx += 256) {
            int mat = idx / 672, r = (idx % 672) / 6, p = idx % 6;
            const float* src = (mat ? vbase : kbase) + (size_t)(kt0 + r) * CC + p * 4;
            uint32_t dst = sb + ((mat ? OV0 : OK0) + r * 28 + p * 4) * 4;
            cp_async16(dst, src);
        }
        cp_commit();
    }

    for (int t = 0; t < 7; t++) {
        int buf = t & 1;
        if (t + 1 < 7) {
            int kt1 = (T0 + t + 1) * KT;
            int nb = buf ^ 1;
            for (int idx = tid; idx < 1344; idx += 256) {
                int mat = idx / 672, r = (idx % 672) / 6, p = idx % 6;
                const float* src = (mat ? vbase : kbase) + (size_t)(kt1 + r) * CC + p * 4;
                uint32_t dst = sb + ((mat ? (nb ? OV1 : OV0) : (nb ? OK1 : OK0)) + r * 28 + p * 4) * 4;
                cp_async16(dst, src);
            }
            cp_commit();
            cp_wait<1>();
        } else {
            cp_wait<0>();
        }
        __syncthreads();

        if (sc_act) {
            const float4* k4 = (const float4*)(sm + (buf ? OK1 : OK0));
            const float4* m4 = (const float4*)(sm + OM);
            float sc[7][4];
            #pragma unroll
            for (int i = 0; i < 7; i++)
                #pragma unroll
                for (int j = 0; j < 4; j++) sc[i][j] = 0.f;
            #pragma unroll
            for (int d4 = 0; d4 < 6; d4++) {
                float4 kv4[4], mm4[7];
                #pragma unroll
                for (int j = 0; j < 4; j++) kv4[j] = k4[(skb + 28 * j) * 7 + d4];
                #pragma unroll
                for (int i = 0; i < 7; i++) mm4[i] = m4[(sq0 + i) * 7 + d4];
                #pragma unroll
                for (int i = 0; i < 7; i++)
                    #pragma unroll
                    for (int j = 0; j < 4; j++)
                        sc[i][j] += mm4[i].x * kv4[j].x + mm4[i].y * kv4[j].y
                                  + mm4[i].z * kv4[j].z + mm4[i].w * kv4[j].w;
            }
            #pragma unroll
            for (int i = 0; i < 7; i++)
                #pragma unroll
                for (int j = 0; j < 4; j++)
                    sm[OS + (sq0 + i) * 112 + skb + 28 * j] = sc[i][j];
        }
        __syncthreads();

        for (int q = wid; q < 49; q += 8) {
            float* row = sm + OS + q * 112;
            float v0 = row[lane], v1 = row[lane + 32], v2 = row[lane + 64];
            float v3 = (lane < 16) ? row[lane + 96] : -1e30f;
            float tmax = fmaxf(fmaxf(v0, v1), fmaxf(v2, v3));
            #pragma unroll
            for (int off = 16; off; off >>= 1)
                tmax = fmaxf(tmax, __shfl_xor_sync(0xffffffffu, tmax, off));
            float mold = sm[OMX + q];
            float mnew = fmaxf(mold, tmax);
            float e0 = expf(v0 - mnew), e1 = expf(v1 - mnew), e2 = expf(v2 - mnew);
            float e3 = (lane < 16) ? expf(v3 - mnew) : 0.f;
            row[lane] = e0; row[lane + 32] = e1; row[lane + 64] = e2;
            if (lane < 16) row[lane + 96] = e3;
            float tsum = e0 + e1 + e2 + e3;
            #pragma unroll
            for (int off = 16; off; off >>= 1)
                tsum += __shfl_xor_sync(0xffffffffu, tsum, off);
            if (lane == 0) {
                float scale = expf(mold - mnew);
                sm[OSC + q] = scale;
                sm[OSM + q] = sm[OSM + q] * scale + tsum;
                sm[OMX + q] = mnew;
            }
        }
        __syncthreads();

        if (pv_act) {
            #pragma unroll
            for (int i = 0; i < 7; i++) {
                float scl = sm[OSC + pq0 + i];
                #pragma unroll
                for (int j = 0; j < 3; j++) acc[i][j] *= scl;
            }
            const float* vb = sm + (buf ? OV1 : OV0);
            for (int lk = 0; lk < 28; lk++) {
                int kk = pvc * 28 + lk;
                float vv0 = vb[kk * 28 + pd0];
                float vv1 = vb[kk * 28 + pd0 + 1];
                float vv2 = vb[kk * 28 + pd0 + 2];
                #pragma unroll
                for (int i = 0; i < 7; i++) {
                    float pp = sm[OS + (pq0 + i) * 112 + kk];
                    acc[i][0] += pp * vv0;
                    acc[i][1] += pp * vv1;
                    acc[i][2] += pp * vv2;
                }
            }
        }
        __syncthreads();
    }

    if (pv_act) {
        #pragma unroll
        for (int i = 0; i < 7; i++)
            #pragma unroll
            for (int j = 0; j < 3; j++)
                sm[OS + ((pq0 + i) * 24 + pd0 + j) * 4 + pvc] = acc[i][j];
    }
    __syncthreads();
    size_t base = (size_t)(bh * NSPLIT + split);
    for (int idx = tid; idx < 1176; idx += 256) {
        float r = sm[OS + idx * 4] + sm[OS + idx * 4 + 1]
                + sm[OS + idx * 4 + 2] + sm[OS + idx * 4 + 3];
        op[base * 1176 + idx] = r;
    }
    if (tid < 49) {
        mxg[base * 49 + tid] = sm[OMX + tid];
        smg[base * 49 + tid] = sm[OSM + tid];
    }
}

// ---------------- attention split merge (log-sum-exp combine) ----------------
__global__ void attn_merge_kernel(const float* __restrict__ op, const float* __restrict__ mxg,
                                  const float* __restrict__ smg, float* __restrict__ o)
{
    __shared__ float wgt[NSPLIT][49];
    __shared__ float den[49];
    int bh = blockIdx.x, tid = threadIdx.x;   // 256 threads
    if (tid < 49) {
        float mx[NSPLIT];
        #pragma unroll
        for (int s = 0; s < NSPLIT; s++) mx[s] = mxg[(size_t)(bh * NSPLIT + s) * 49 + tid];
        float ms = fmaxf(fmaxf(mx[0], mx[1]), fmaxf(mx[2], mx[3]));
        float d = 0.f;
        #pragma unroll
        for (int s = 0; s < NSPLIT; s++) {
            float ww = expf(mx[s] - ms);
            wgt[s][tid] = ww;
            d += smg[(size_t)(bh * NSPLIT + s) * 49 + tid] * ww;
        }
        den[tid] = d;
    }
    __syncthreads();
    for (int idx = tid; idx < 1176; idx += 256) {
        int q = idx / 24;
        float r = 0.f;
        #pragma unroll
        for (int s = 0; s < NSPLIT; s++)
            r += op[(size_t)(bh * NSPLIT + s) * 1176 + idx] * wgt[s][q];
        o[(size_t)bh * 1176 + idx] = r / den[q];
    }
}

// ---------------- bilinear upsample of o -> cat[:,384:576] ----------------
__global__ void upsample_cat_kernel(const float* __restrict__ o, __half* __restrict__ cat)
{
    int x = blockIdx.x, y = blockIdx.y, b = blockIdx.z;
    int c = threadIdx.x;   // 192
    float fy = (y + 0.5f) * 0.125f - 0.5f;
    float fx = (x + 0.5f) * 0.125f - 0.5f;
    int y0 = (int)floorf(fy); float ty = fy - (float)y0;
    int x0 = (int)floorf(fx); float tx = fx - (float)x0;
    int y0c = max(y0, 0), y1c = min(y0 + 1, 6);
    int x0c = max(x0, 0), x1c = min(x0 + 1, 6);

    int h = c / HD2, d = c % HD2;
    const float* ob = o + ((size_t)(b * NHD + h) * 49) * HD2 + d;
    float v00 = ob[(y0c * 7 + x0c) * HD2], v01 = ob[(y0c * 7 + x1c) * HD2];
    float v10 = ob[(y1c * 7 + x0c) * HD2], v11 = ob[(y1c * 7 + x1c) * HD2];
    float v = (1.f - ty) * ((1.f - tx) * v00 + tx * v01) + ty * ((1.f - tx) * v10 + tx * v11);
    cat[(((size_t)b * HH + y) * WW + x) * 768 + 384 + c] = __float2half(v);
}

// ---------------- launch (serial; cat built by producer epilogues) ----------------
extern "C" void kernel_launch(void* const* d_in, const int* in_sizes, int n_in,
                              void* d_out, int out_size)
{
    const float* x       = (const float*)d_in[0];
    const float* x_e     = (const float*)d_in[1];
    const float* norm_w  = (const float*)d_in[2];
    const float* norm_b  = (const float*)d_in[3];
    const float* norme_w = (const float*)d_in[4];
    const float* norme_b = (const float*)d_in[5];
    const float* q_w     = (const float*)d_in[6];
    const float* q_b     = (const float*)d_in[7];
    const float* qcut_w  = (const float*)d_in[8];
    const float* qcut_b  = (const float*)d_in[9];
    const float* a_w     = (const float*)d_in[10];
    const float* a_b     = (const float*)d_in[11];
    const float* l_w     = (const float*)d_in[12];
    const float* l_b     = (const float*)d_in[13];
    const float* conv_w  = (const float*)d_in[14];
    const float* conv_b  = (const float*)d_in[15];
    const float* econv_w = (const float*)d_in[16];
    const float* econv_b = (const float*)d_in[17];
    const float* efore_w = (const float*)d_in[18];
    const float* efore_b = (const float*)d_in[19];
    const float* eback_w = (const float*)d_in[20];
    const float* eback_b = (const float*)d_in[21];
    const float* kv_w    = (const float*)d_in[22];
    const float* kv_b    = (const float*)d_in[23];
    const float* scl_w   = (const float*)d_in[24];
    const float* scl_b   = (const float*)d_in[25];
    const float* proj_w  = (const float*)d_in[26];
    const float* proj_b  = (const float*)d_in[27];
    const float* proje_w = (const float*)d_in[28];
    const float* proje_b = (const float*)d_in[29];
    float* out = (float*)d_out;
    float* out_x  = out;
    float* out_xe = out + (size_t)MM * CC;

    __half *xn,*xen,*qb,*cutb,*lx,*clx,*ef,*efc,*catb;
    __half *w3,*w2,*tkv,*ta,*tefore,*teback;
    float *b3,*b2,*kvb,*mb,*ob,*opb,*mxb,*smb;
    cudaGetSymbolAddress((void**)&xn,   g_xn);
    cudaGetSymbolAddress((void**)&xen,  g_xen);
    cudaGetSymbolAddress((void**)&qb,   g_q);
    cudaGetSymbolAddress((void**)&cutb, g_cut);
    cudaGetSymbolAddress((void**)&lx,   g_lx);
    cudaGetSymbolAddress((void**)&clx,  g_clx);
    cudaGetSymbolAddress((void**)&kvb,  g_kv);
    cudaGetSymbolAddress((void**)&ef,   g_ef);
    cudaGetSymbolAddress((void**)&efc,  g_efc);
    cudaGetSymbolAddress((void**)&mb,   g_m);
    cudaGetSymbolAddress((void**)&ob,   g_o);
    cudaGetSymbolAddress((void**)&opb,  g_op);
    cudaGetSymbolAddress((void**)&mxb,  g_mx);
    cudaGetSymbolAddress((void**)&smb,  g_sm2);
    cudaGetSymbolAddress((void**)&catb, g_cat);
    cudaGetSymbolAddress((void**)&w3,     g_w3);
    cudaGetSymbolAddress((void**)&b3,     g_b3);
    cudaGetSymbolAddress((void**)&w2,     g_w2);
    cudaGetSymbolAddress((void**)&b2,     g_b2);
    cudaGetSymbolAddress((void**)&tkv,    g_tkv);
    cudaGetSymbolAddress((void**)&ta,     g_ta);
    cudaGetSymbolAddress((void**)&tefore, g_tefore);
    cudaGetSymbolAddress((void**)&teback, g_teback);

    cudaFuncSetAttribute(h16_gemm_kernel, cudaFuncAttributeMaxDynamicSharedMemorySize, GEMM_SMEM);
    cudaFuncSetAttribute(h16_gemm_routed, cudaFuncAttributeMaxDynamicSharedMemorySize, GEMM_SMEM);
    cudaFuncSetAttribute(attn_kernel, cudaFuncAttributeMaxDynamicSharedMemorySize, ATTN_SMEM);

    dim3 gN384(3, MM / 128), gN192(2, MM / 128);

    // 0) all weight transposes + bias concat in one launch
    transpose_all_kernel<<<4999, 256>>>(q_w, l_w, a_w, kv_w, qcut_w, efore_w, eback_w,
                                        proj_w, proje_w,
                                        q_b, l_b, qcut_b, proj_b, proje_b,
                                        w3, b3, w2, b2, tkv, ta, tefore, teback);

    // 1) both LayerNorms in one launch
    ln_kernel<<<LN_BLOCKS_X + MM / 8, 256>>>(x, norm_w, norm_b, xn,
                                             x_e, norme_w, norme_b, xen);

    // 2) pooled shortcut queries -> m (scaled, fp32)
    pool_scl_kernel<<<BB * 49, 192>>>(xn, xen, scl_w, scl_b, mb);

    // 3) fused q + lx(gelu) + cut GEMM (one launch, shared A = xn)
    h16_gemm_routed<<<dim3(8, MM / 128), 256, GEMM_SMEM>>>(
        xn, w3, b3, nullptr, qb, lx, cutb, nullptr, nullptr, 1024, 384, 0);

    // 4) depthwise conv on lx, then a-GEMM (epilogue writes q*a into cat[:,0:384])
    //    and kv GEMM (fp32 out for attention)
    dwconv7_kernel<<<dim3(4, 4, BB * (CC / 16)), 224>>>(lx, conv_w, conv_b, clx, CC);
    h16_gemm_routed<<<dim3(3, MM / 128), 256, GEMM_SMEM>>>(
        clx, ta, a_b, qb, catb, nullptr, nullptr, nullptr, nullptr, 384, 384, 2);
    h16_gemm_kernel<<<gN384, 256, GEMM_SMEM>>>(lx, tkv, kv_b, kvb, nullptr, 384, 384);

    // 5) flash attention (split-K x4) + merge + upsample into cat[:,384:576]
    attn_kernel<<<BB * NHD * NSPLIT, 256, ATTN_SMEM>>>(kvb, mb, opb, mxb, smb);
    attn_merge_kernel<<<BB * NHD, 256>>>(opb, mxb, smb, ob);
    upsample_cat_kernel<<<dim3(WW, HH, BB), C2>>>(ob, catb);

    // 6) x_e depthwise branch (eback epilogue writes cut*xe2 into cat[:,576:768])
    h16_gemm_kernel<<<gN192, 256, GEMM_SMEM>>>(xen, tefore, efore_b, nullptr, ef, 192, 192);
    dwconv7_kernel<<<dim3(4, 4, BB * (C2 / 16)), 224>>>(ef, econv_w, econv_b, efc, C2);
    h16_gemm_routed<<<dim3(2, MM / 128), 256, GEMM_SMEM>>>(
        efc, teback, eback_b, cutb, catb, nullptr, nullptr, nullptr, nullptr, 256, 192, 3);

    // 7) fused output projection (fp32 out)
    h16_gemm_routed<<<dim3(5, MM / 128), 256, GEMM_SMEM>>>(
        catb, w2, b2, nullptr, nullptr, nullptr, nullptr, out_x, out_xe, 640, 768, 1);
}